// round 12
// baseline (speedup 1.0000x reference)
#include <cuda_runtime.h>
#include <cuda_fp16.h>
#include <math.h>
#include <stdint.h>

// ---------------- problem constants ----------------
#define BB      2
#define LL      1024
#define DD      768
#define EE      1536
#define NN      16
#define DDELTA  48
#define DCONV   4
#define VV      50280
#define NLAYERS 2
#define ML      (BB*LL)   // 2048 rows
#define PKN     (DDELTA + 2*NN)   // 80 packed rows: [delta1 48 | B 16 | C 16]

// ---------------- scratch (no allocs allowed) ----------------
__device__ float g_resid[BB*LL*DD];
__device__ float g_skip[BB*LL*EE];
__device__ float g_xi  [BB*LL*EE];
__device__ float g_xc  [BB*LL*EE];
__device__ float g_dbc [ML*PKN];          // packed [d1 | B | C] per row
__device__ float g_delta[BB*LL*EE];

// fp16 weight / activation copies
__device__ __align__(16) __half h_lm  [VV*DD];
__device__ __align__(16) __half h_skip[NLAYERS*EE*DD];
__device__ __align__(16) __half h_in  [NLAYERS*EE*DD];
__device__ __align__(16) __half h_out [NLAYERS*DD*EE];
__device__ __align__(16) __half h_Wsm [NLAYERS*PKN*EE];   // packed small weights
__device__ __align__(16) __half h_xn  [ML*DD];
__device__ __align__(16) __half h_xc  [ML*EE];
__device__ __align__(16) __half h_y   [ML*EE];

// ---------------- helpers ----------------
__inline__ __device__ float warpReduceSum(float v) {
    #pragma unroll
    for (int o = 16; o > 0; o >>= 1) v += __shfl_down_sync(0xffffffffu, v, o);
    return v;
}

__device__ __forceinline__ uint32_t f2tf32(float f) {
    uint32_t u;
    asm("cvt.rna.tf32.f32 %0, %1;" : "=r"(u) : "f"(f));
    return u;
}

__device__ __forceinline__ void mma_f16(float* c, const uint32_t* a, const uint32_t* b) {
    asm volatile(
        "mma.sync.aligned.m16n8k16.row.col.f32.f16.f16.f32 "
        "{%0,%1,%2,%3}, {%4,%5,%6,%7}, {%8,%9}, {%0,%1,%2,%3};\n"
        : "+f"(c[0]), "+f"(c[1]), "+f"(c[2]), "+f"(c[3])
        : "r"(a[0]), "r"(a[1]), "r"(a[2]), "r"(a[3]), "r"(b[0]), "r"(b[1]));
}

__device__ __forceinline__ void mma_tf32(float* c, const uint32_t* a, const uint32_t* b) {
    asm volatile(
        "mma.sync.aligned.m16n8k8.row.col.f32.tf32.tf32.f32 "
        "{%0,%1,%2,%3}, {%4,%5,%6,%7}, {%8,%9}, {%0,%1,%2,%3};\n"
        : "+f"(c[0]), "+f"(c[1]), "+f"(c[2]), "+f"(c[3])
        : "r"(a[0]), "r"(a[1]), "r"(a[2]), "r"(a[3]), "r"(b[0]), "r"(b[1]));
}

__device__ __forceinline__ void ldsm_x4(uint32_t& r0, uint32_t& r1, uint32_t& r2,
                                        uint32_t& r3, uint32_t saddr) {
    asm volatile("ldmatrix.sync.aligned.m8n8.x4.shared.b16 {%0,%1,%2,%3}, [%4];"
                 : "=r"(r0), "=r"(r1), "=r"(r2), "=r"(r3) : "r"(saddr));
}

__device__ __forceinline__ void cp16(uint32_t dst, const void* src) {
    asm volatile("cp.async.cg.shared.global [%0], [%1], 16;" :: "r"(dst), "l"(src));
}
__device__ __forceinline__ void cp16p(uint32_t dst, const void* src, int sz) {
    asm volatile("cp.async.cg.shared.global [%0], [%1], 16, %2;"
                 :: "r"(dst), "l"(src), "r"(sz));
}
__device__ __forceinline__ void cp_commit() {
    asm volatile("cp.async.commit_group;");
}
template<int NWAIT>
__device__ __forceinline__ void cp_wait() {
    asm volatile("cp.async.wait_group %0;" :: "n"(NWAIT));
}

// ---------------- fp32 -> fp16 convert ----------------
__global__ void f2h_kernel(const float* __restrict__ s, __half* __restrict__ d, int n4) {
    int i = blockIdx.x * blockDim.x + threadIdx.x;
    if (i >= n4) return;
    float4 v = reinterpret_cast<const float4*>(s)[i];
    __half2 h0 = __floats2half2_rn(v.x, v.y);
    __half2 h1 = __floats2half2_rn(v.z, v.w);
    uint2 t;
    t.x = *reinterpret_cast<uint32_t*>(&h0);
    t.y = *reinterpret_cast<uint32_t*>(&h1);
    reinterpret_cast<uint2*>(d)[i] = t;
}

struct F2HJobs {
    const float* s[8];
    __half*      d[8];
    int          n4[8];
};

__global__ void f2h_multi(F2HJobs jobs) {
    int j = blockIdx.y;
    int n4 = jobs.n4[j];
    const float4* s = reinterpret_cast<const float4*>(jobs.s[j]);
    uint2*        d = reinterpret_cast<uint2*>(jobs.d[j]);
    for (int i = blockIdx.x * blockDim.x + threadIdx.x; i < n4;
         i += gridDim.x * blockDim.x) {
        float4 v = s[i];
        __half2 h0 = __floats2half2_rn(v.x, v.y);
        __half2 h1 = __floats2half2_rn(v.z, v.w);
        uint2 t;
        t.x = *reinterpret_cast<uint32_t*>(&h0);
        t.y = *reinterpret_cast<uint32_t*>(&h1);
        d[i] = t;
    }
}

// ================= FP16 HMMA GEMM, 128x128 CTA, 2-stage static smem (PINNED) =================
#define SSH 40                         // halfs per smem row (32 + pad 8)
#define HBUF (128 * SSH * 2)           // bytes per buffer

__device__ __forceinline__ void issue_chunk(uint32_t sAbuf, uint32_t sBbuf,
                                            const __half* __restrict__ Ab,
                                            const __half* __restrict__ Wb,
                                            int K, int k0, int nBase, int N, int tid) {
    #pragma unroll
    for (int f = 0; f < 2; f++) {
        int idx = f * 256 + tid;
        int r = idx >> 2, g = idx & 3;
        cp16(sAbuf + (uint32_t)(r * SSH + g * 8) * 2, Ab + (size_t)r * K + k0 + g * 8);
        int sz = (nBase + r < N) ? 16 : 0;
        cp16p(sBbuf + (uint32_t)(r * SSH + g * 8) * 2, Wb + (size_t)r * K + k0 + g * 8, sz);
    }
}

template<int EPI>
__global__ void __launch_bounds__(256)
gemm_h(const __half* __restrict__ A,
       const __half* __restrict__ W0, const __half* __restrict__ W1,
       float* __restrict__ C0, float* __restrict__ C1,
       int M, int N, int K) {
    __shared__ __half As[2][128][SSH];
    __shared__ __half Bs[2][128][SSH];

    const __half* W = blockIdx.z ? W1 : W0;
    float*        C = blockIdx.z ? C1 : C0;

    const int tid  = threadIdx.x;
    const int lane = tid & 31;
    const int warp = tid >> 5;
    const int wm   = warp >> 2;
    const int wn   = warp & 3;
    const int r    = lane >> 2;
    const int c    = lane & 3;

    const int mBase = blockIdx.y * 128;
    const int nBase = blockIdx.x * 128;
    const int nk = K / 32;
    const __half* Ab = A + (size_t)mBase * K;
    const __half* Wb = W + (size_t)nBase * K;

    const int mat  = lane >> 3;
    const int mrow = lane & 7;
    const int aOff = (((wm * 64) + (mat & 1) * 8 + mrow) * SSH + ((mat >> 1) * 8)) * 2;
    const int bOff = (((wn * 32) + (mat >> 1) * 8 + mrow) * SSH + ((mat & 1) * 8)) * 2;
    const uint32_t sA = (uint32_t)__cvta_generic_to_shared(&As[0][0][0]);
    const uint32_t sB = (uint32_t)__cvta_generic_to_shared(&Bs[0][0][0]);

    float acc[4][4][4];
    #pragma unroll
    for (int i = 0; i < 4; i++)
        #pragma unroll
        for (int j = 0; j < 4; j++)
            #pragma unroll
            for (int k = 0; k < 4; k++) acc[i][j][k] = 0.f;

    issue_chunk(sA, sB, Ab, Wb, K, 0, nBase, N, tid);
    cp_commit();
    if (nk > 1) {
        issue_chunk(sA + HBUF, sB + HBUF, Ab, Wb, K, 32, nBase, N, tid);
        cp_commit();
    }

    for (int ch = 0; ch < nk; ch++) {
        if (ch + 1 < nk) cp_wait<1>(); else cp_wait<0>();
        __syncthreads();

        const uint32_t aBase = sA + (ch & 1) * HBUF + aOff;
        const uint32_t bBase = sB + (ch & 1) * HBUF + bOff;
        #pragma unroll
        for (int ks = 0; ks < 32; ks += 16) {
            uint32_t af[4][4], bf[4][2];
            #pragma unroll
            for (int mt = 0; mt < 4; mt++)
                ldsm_x4(af[mt][0], af[mt][1], af[mt][2], af[mt][3],
                        aBase + (uint32_t)(mt * 16 * SSH + ks) * 2);
            #pragma unroll
            for (int np = 0; np < 2; np++)
                ldsm_x4(bf[2*np][0], bf[2*np][1], bf[2*np+1][0], bf[2*np+1][1],
                        bBase + (uint32_t)(np * 16 * SSH + ks) * 2);
            #pragma unroll
            for (int mt = 0; mt < 4; mt++)
                #pragma unroll
                for (int nt = 0; nt < 4; nt++)
                    mma_f16(acc[mt][nt], af[mt], bf[nt]);
        }
        __syncthreads();

        if (ch + 2 < nk) {
            issue_chunk(sA + (ch & 1) * HBUF, sB + (ch & 1) * HBUF,
                        Ab, Wb, K, (ch + 2) * 32, nBase, N, tid);
            cp_commit();
        }
    }

    #pragma unroll
    for (int mt = 0; mt < 4; mt++) {
        #pragma unroll
        for (int nt = 0; nt < 4; nt++) {
            int mg0 = mBase + wm * 64 + mt * 16 + r;
            int ng0 = nBase + wn * 32 + nt * 8 + 2 * c;
            #pragma unroll
            for (int ri = 0; ri < 2; ri++) {
                #pragma unroll
                for (int ci = 0; ci < 2; ci++) {
                    int m = mg0 + ri * 8;
                    int n = ng0 + ci;
                    float v = acc[mt][nt][ri * 2 + ci];
                    if (n < N) {
                        size_t idx = (size_t)m * N + n;
                        if (EPI == 1) C[idx] += v; else C[idx] = v;
                    }
                }
            }
        }
    }
}

// ---------------- TF32 GEMM with softplus epilogue (K=48 path, strided A) ----------------
#define SST 20
__global__ void __launch_bounds__(256)
gemm_tf32_sp(const float* __restrict__ A, int lda,
             const float* __restrict__ W,
             const float* __restrict__ bias, float* __restrict__ C,
             int M, int N, int K) {
    __shared__ uint32_t As[2][128][SST];
    __shared__ uint32_t Bs[2][128][SST];

    const int tid  = threadIdx.x;
    const int lane = tid & 31;
    const int warp = tid >> 5;
    const int wm   = warp >> 2;
    const int wn   = warp & 3;
    const int r    = lane >> 2;
    const int c    = lane & 3;

    const int ldRow = tid >> 2;
    const int ldCol = (tid & 3) * 4;

    const int mBase = blockIdx.y * 128;
    const int nBase = blockIdx.x * 128;
    const int nk = K / 16;

    const int mat = lane >> 3;
    const int mrow = lane & 7;
    const int aOff = (((wm * 64) + (mat & 1) * 8 + mrow) * SST + ((mat >> 1) * 4)) * 4;
    const int bOff = (((wn * 32) + (mat >> 1) * 8 + mrow) * SST + ((mat & 1) * 4)) * 4;
    const uint32_t sA = (uint32_t)__cvta_generic_to_shared(&As[0][0][0]);
    const uint32_t sB = (uint32_t)__cvta_generic_to_shared(&Bs[0][0][0]);
    const int BUF = 128 * SST * 4;

    float acc[4][4][4];
    #pragma unroll
    for (int i = 0; i < 4; i++)
        #pragma unroll
        for (int j = 0; j < 4; j++)
            #pragma unroll
            for (int k = 0; k < 4; k++) acc[i][j][k] = 0.f;

    float4 a0p, a1p, w0p, w1p;
    {
        const float* ap = A + (size_t)(mBase + ldRow) * lda + ldCol;
        a0p = *reinterpret_cast<const float4*>(ap);
        a1p = *reinterpret_cast<const float4*>(ap + (size_t)64 * lda);
        int n0 = nBase + ldRow, n1 = n0 + 64;
        w0p = make_float4(0.f,0.f,0.f,0.f);
        w1p = w0p;
        if (n0 < N) w0p = *reinterpret_cast<const float4*>(W + (size_t)n0 * K + ldCol);
        if (n1 < N) w1p = *reinterpret_cast<const float4*>(W + (size_t)n1 * K + ldCol);
    }
    {
        uint4 t;
        t.x=f2tf32(a0p.x); t.y=f2tf32(a0p.y); t.z=f2tf32(a0p.z); t.w=f2tf32(a0p.w);
        *reinterpret_cast<uint4*>(&As[0][ldRow][ldCol]) = t;
        t.x=f2tf32(a1p.x); t.y=f2tf32(a1p.y); t.z=f2tf32(a1p.z); t.w=f2tf32(a1p.w);
        *reinterpret_cast<uint4*>(&As[0][ldRow+64][ldCol]) = t;
        t.x=f2tf32(w0p.x); t.y=f2tf32(w0p.y); t.z=f2tf32(w0p.z); t.w=f2tf32(w0p.w);
        *reinterpret_cast<uint4*>(&Bs[0][ldRow][ldCol]) = t;
        t.x=f2tf32(w1p.x); t.y=f2tf32(w1p.y); t.z=f2tf32(w1p.z); t.w=f2tf32(w1p.w);
        *reinterpret_cast<uint4*>(&Bs[0][ldRow+64][ldCol]) = t;
    }
    __syncthreads();

    int cur = 0;
    for (int ch = 0; ch < nk; ch++) {
        if (ch + 1 < nk) {
            int k0 = (ch + 1) * 16;
            const float* ap = A + (size_t)(mBase + ldRow) * lda + k0 + ldCol;
            a0p = *reinterpret_cast<const float4*>(ap);
            a1p = *reinterpret_cast<const float4*>(ap + (size_t)64 * lda);
            int n0 = nBase + ldRow, n1 = n0 + 64;
            w0p = make_float4(0.f,0.f,0.f,0.f);
            w1p = w0p;
            if (n0 < N) w0p = *reinterpret_cast<const float4*>(W + (size_t)n0 * K + k0 + ldCol);
            if (n1 < N) w1p = *reinterpret_cast<const float4*>(W + (size_t)n1 * K + k0 + ldCol);
        }

        const uint32_t aBase = sA + cur * BUF + aOff;
        const uint32_t bBase = sB + cur * BUF + bOff;
        #pragma unroll
        for (int ks = 0; ks < 16; ks += 8) {
            uint32_t af[4][4], bf[4][2];
            #pragma unroll
            for (int mt = 0; mt < 4; mt++)
                ldsm_x4(af[mt][0], af[mt][1], af[mt][2], af[mt][3],
                        aBase + (mt * 16 * SST + ks) * 4);
            #pragma unroll
            for (int np = 0; np < 2; np++)
                ldsm_x4(bf[2*np][0], bf[2*np][1], bf[2*np+1][0], bf[2*np+1][1],
                        bBase + (np * 16 * SST + ks) * 4);
            #pragma unroll
            for (int mt = 0; mt < 4; mt++)
                #pragma unroll
                for (int nt = 0; nt < 4; nt++)
                    mma_tf32(acc[mt][nt], af[mt], bf[nt]);
        }

        if (ch + 1 < nk) {
            int nxt = cur ^ 1;
            uint4 t;
            t.x=f2tf32(a0p.x); t.y=f2tf32(a0p.y); t.z=f2tf32(a0p.z); t.w=f2tf32(a0p.w);
            *reinterpret_cast<uint4*>(&As[nxt][ldRow][ldCol]) = t;
            t.x=f2tf32(a1p.x); t.y=f2tf32(a1p.y); t.z=f2tf32(a1p.z); t.w=f2tf32(a1p.w);
            *reinterpret_cast<uint4*>(&As[nxt][ldRow+64][ldCol]) = t;
            t.x=f2tf32(w0p.x); t.y=f2tf32(w0p.y); t.z=f2tf32(w0p.z); t.w=f2tf32(w0p.w);
            *reinterpret_cast<uint4*>(&Bs[nxt][ldRow][ldCol]) = t;
            t.x=f2tf32(w1p.x); t.y=f2tf32(w1p.y); t.z=f2tf32(w1p.z); t.w=f2tf32(w1p.w);
            *reinterpret_cast<uint4*>(&Bs[nxt][ldRow+64][ldCol]) = t;
        }
        __syncthreads();
        cur ^= 1;
    }

    #pragma unroll
    for (int mt = 0; mt < 4; mt++) {
        #pragma unroll
        for (int nt = 0; nt < 4; nt++) {
            int mg0 = mBase + wm * 64 + mt * 16 + r;
            int ng0 = nBase + wn * 32 + nt * 8 + 2 * c;
            #pragma unroll
            for (int ri = 0; ri < 2; ri++) {
                #pragma unroll
                for (int ci = 0; ci < 2; ci++) {
                    int m = mg0 + ri * 8;
                    int n = ng0 + ci;
                    if (n < N) {
                        float s = acc[mt][nt][ri * 2 + ci] + bias[n];
                        C[(size_t)m * N + n] = (s > 20.f) ? s : log1pf(expf(s));
                    }
                }
            }
        }
    }
}

// ---------------- embedding gather ----------------
__global__ void embed_kernel(const int* __restrict__ tokens,
                             const float* __restrict__ emb,
                             float* __restrict__ resid) {
    int row = blockIdx.x;
    int t = tokens[row];
    const float* src = emb + (size_t)t * DD;
    float* dst = resid + (size_t)row * DD;
    for (int i = threadIdx.x; i < DD; i += blockDim.x) dst[i] = src[i];
}

// ---------------- rmsnorm -> fp16 output ----------------
__global__ void rmsnorm_h_kernel(const float* __restrict__ x,
                                 const float* __restrict__ w,
                                 __half* __restrict__ out) {
    int row = blockIdx.x;
    const float* xr = x + (size_t)row * DD;
    float s = 0.f;
    for (int i = threadIdx.x; i < DD; i += 256) { float v = xr[i]; s = fmaf(v, v, s); }
    s = warpReduceSum(s);
    __shared__ float red[8];
    int warp = threadIdx.x >> 5, lane = threadIdx.x & 31;
    if (lane == 0) red[warp] = s;
    __syncthreads();
    if (warp == 0) {
        float v = (lane < 8) ? red[lane] : 0.f;
        v = warpReduceSum(v);
        if (lane == 0) red[0] = rsqrtf(v / (float)DD + 1e-5f);
    }
    __syncthreads();
    float scale = red[0];
    __half* o = out + (size_t)row * DD;
    for (int i = threadIdx.x; i < DD; i += 256)
        o[i] = __float2half_rn(xr[i] * scale * w[i]);
}

// ---------------- depthwise causal conv1d + bias + silu (fp32 + fp16 out) ----------------
__global__ void conv_silu_kernel(const float* __restrict__ xi,
                                 const float* __restrict__ cw,
                                 const float* __restrict__ cb,
                                 float* __restrict__ out,
                                 __half* __restrict__ outh) {
    int idx = blockIdx.x * blockDim.x + threadIdx.x;
    if (idx >= BB * LL * EE) return;
    int e  = idx % EE;
    int bl = idx / EE;
    int l  = bl % LL;
    float acc = cb[e];
    #pragma unroll
    for (int k = 0; k < DCONV; k++) {
        int ls = l - (DCONV - 1) + k;
        if (ls >= 0)
            acc = fmaf(cw[e * DCONV + k],
                       xi[(size_t)(bl - (DCONV - 1) + k) * EE + e], acc);
    }
    float v = acc / (1.f + __expf(-acc));
    out[idx] = v;
    outh[idx] = __float2half_rn(v);
}

// ---------------- selective scan (4 threads/channel) + fused output gating ----------------
// grid = BB*EE*4/256 = 48 CTAs. Quad (tid&3) = state group; shfl-reduce y over quad.
// ng==0 applies (y + x*wD) * silu(skip) and writes fp16 directly (no y buffer).
__global__ void __launch_bounds__(256)
scan_kernel(const float* __restrict__ delta, const float* __restrict__ x,
            const float* __restrict__ Bm, const float* __restrict__ Cm, int ldbc,
            const float* __restrict__ A_log,
            const float* __restrict__ skip, const float* __restrict__ wD,
            __half* __restrict__ yh) {
    int ch = blockIdx.x * 64 + (threadIdx.x >> 2);   // 0 .. BB*EE-1
    int ng = threadIdx.x & 3;                         // state group 0..3
    int b  = ch / EE;
    int e  = ch % EE;

    float a[4], h[4];
    #pragma unroll
    for (int j = 0; j < 4; j++) {
        a[j] = -expf(A_log[e * NN + ng * 4 + j]);
        h[j] = 0.f;
    }
    const float wd = wD[e];

    const size_t row0 = (size_t)b * LL;
    #pragma unroll 2
    for (int l = 0; l < LL; l++) {
        size_t row = row0 + l;
        float d  = delta[row * EE + e];
        float xv = x    [row * EE + e];
        float sk = skip [row * EE + e];
        float dx = d * xv;
        float4 Bv = *reinterpret_cast<const float4*>(Bm + row * ldbc + ng * 4);
        float4 Cv = *reinterpret_cast<const float4*>(Cm + row * ldbc + ng * 4);
        float yacc;
        h[0] = __expf(d * a[0]) * h[0] + dx * Bv.x;
        h[1] = __expf(d * a[1]) * h[1] + dx * Bv.y;
        h[2] = __expf(d * a[2]) * h[2] + dx * Bv.z;
        h[3] = __expf(d * a[3]) * h[3] + dx * Bv.w;
        yacc = h[0] * Cv.x;
        yacc = fmaf(h[1], Cv.y, yacc);
        yacc = fmaf(h[2], Cv.z, yacc);
        yacc = fmaf(h[3], Cv.w, yacc);
        yacc += __shfl_xor_sync(0xffffffffu, yacc, 1);
        yacc += __shfl_xor_sync(0xffffffffu, yacc, 2);
        if (ng == 0) {
            float v = fmaf(xv, wd, yacc);
            yh[row * EE + e] = __float2half_rn(v * (sk / (1.f + __expf(-sk))));
        }
    }
}

// ---------------- launch ----------------
extern "C" void kernel_launch(void* const* d_in, const int* in_sizes, int n_in,
                              void* d_out, int out_size) {
    (void)in_sizes; (void)n_in; (void)out_size;

    const int*   tokens = (const int*)  d_in[0];
    const float* emb    = (const float*)d_in[1];
    const float* norm_w = (const float*)d_in[2];
    const float* skip_w = (const float*)d_in[3];
    const float* in_w   = (const float*)d_in[4];
    const float* conv_w = (const float*)d_in[5];
    const float* conv_b = (const float*)d_in[6];
    const float* Wd1    = (const float*)d_in[7];
    const float* Wd2_w  = (const float*)d_in[8];
    const float* Wd2_b  = (const float*)d_in[9];
    const float* WB     = (const float*)d_in[10];
    const float* WC     = (const float*)d_in[11];
    const float* A_log  = (const float*)d_in[12];
    const float* W_D    = (const float*)d_in[13];
    const float* out_w  = (const float*)d_in[14];
    const float* fnw    = (const float*)d_in[15];
    const float* lm     = (const float*)d_in[16];
    float* out = (float*)d_out;

    float *resid, *skip, *xi, *xc, *dbc, *delta;
    cudaGetSymbolAddress((void**)&resid, g_resid);
    cudaGetSymbolAddress((void**)&skip,  g_skip);
    cudaGetSymbolAddress((void**)&xi,    g_xi);
    cudaGetSymbolAddress((void**)&xc,    g_xc);
    cudaGetSymbolAddress((void**)&dbc,   g_dbc);
    cudaGetSymbolAddress((void**)&delta, g_delta);

    __half *hlm, *hskip, *hin, *hout, *hWsm, *hxn, *hxc, *hy;
    cudaGetSymbolAddress((void**)&hlm,   h_lm);
    cudaGetSymbolAddress((void**)&hskip, h_skip);
    cudaGetSymbolAddress((void**)&hin,   h_in);
    cudaGetSymbolAddress((void**)&hout,  h_out);
    cudaGetSymbolAddress((void**)&hWsm,  h_Wsm);
    cudaGetSymbolAddress((void**)&hxn,   h_xn);
    cudaGetSymbolAddress((void**)&hxc,   h_xc);
    cudaGetSymbolAddress((void**)&hy,    h_y);

    // ---- weight conversions: 3 launches total ----
    {
        int n4 = VV * DD / 4;
        f2h_kernel<<<(n4 + 255) / 256, 256>>>(lm, hlm, n4);

        F2HJobs jb = {};
        jb.s[0] = skip_w; jb.d[0] = hskip; jb.n4[0] = NLAYERS * EE * DD / 4;
        jb.s[1] = in_w;   jb.d[1] = hin;   jb.n4[1] = NLAYERS * EE * DD / 4;
        f2h_multi<<<dim3(2304, 2, 1), 256>>>(jb);

        F2HJobs jc = {};
        jc.s[0] = out_w; jc.d[0] = hout; jc.n4[0] = NLAYERS * DD * EE / 4;
        int j = 1;
        for (int l = 0; l < NLAYERS; l++) {
            jc.s[j] = Wd1 + (size_t)l * DDELTA * EE;
            jc.d[j] = hWsm + (size_t)l * PKN * EE;
            jc.n4[j] = DDELTA * EE / 4; j++;
            jc.s[j] = WB + (size_t)l * NN * EE;
            jc.d[j] = hWsm + (size_t)l * PKN * EE + (size_t)DDELTA * EE;
            jc.n4[j] = NN * EE / 4; j++;
            jc.s[j] = WC + (size_t)l * NN * EE;
            jc.d[j] = hWsm + (size_t)l * PKN * EE + (size_t)(DDELTA + NN) * EE;
            jc.n4[j] = NN * EE / 4; j++;
        }
        f2h_multi<<<dim3(2304, 7, 1), 256>>>(jc);
    }

    const int totE = BB * LL * EE;
    const dim3 gE2((EE  + 127) / 128, ML / 128, 2);  // skip + in fused
    const dim3 gP ((PKN + 127) / 128, ML / 128, 1);  // packed d1|B|C
    const dim3 gDe((EE  + 127) / 128, ML / 128, 1);  // tf32 softplus
    const dim3 gO ((DD  + 127) / 128, ML / 128, 1);
    const dim3 gV ((VV  + 127) / 128, ML / 128, 1);

    embed_kernel<<<ML, 256>>>(tokens, emb, resid);

    for (int lyr = 0; lyr < NLAYERS; ++lyr) {
        rmsnorm_h_kernel<<<ML, 256>>>(resid, norm_w + lyr * DD, hxn);

        gemm_h<0><<<gE2, 256>>>(hxn,
            hskip + (size_t)lyr * EE * DD, hin + (size_t)lyr * EE * DD,
            skip, xi, ML, EE, DD);

        conv_silu_kernel<<<(totE + 255) / 256, 256>>>(xi, conv_w + lyr * EE * DCONV,
                                                      conv_b + lyr * EE, xc, hxc);

        // packed small GEMM: [d1 48 | B 16 | C 16] = xc @ Wsm^T
        gemm_h<0><<<gP, 256>>>(hxc, hWsm + (size_t)lyr * PKN * EE, nullptr,
                               dbc, nullptr, ML, PKN, EE);

        gemm_tf32_sp<<<gDe, 256>>>(dbc, PKN, Wd2_w + (size_t)lyr * EE * DDELTA,
                                   Wd2_b + lyr * EE, delta, ML, EE, DDELTA);

        scan_kernel<<<BB * EE * 4 / 256, 256>>>(delta, xc,
                                                dbc + DDELTA, dbc + DDELTA + NN, PKN,
                                                A_log + lyr * EE * NN,
                                                skip, W_D + lyr * EE, hy);

        gemm_h<1><<<gO, 256>>>(hy, hout + (size_t)lyr * DD * EE, nullptr,
                               resid, nullptr, ML, DD, EE);
    }

    rmsnorm_h_kernel<<<ML, 256>>>(resid, fnw, hxn);
    gemm_h<0><<<gV, 256>>>(hxn, hlm, nullptr, out, nullptr, ML, VV, DD);
}

// round 13
// speedup vs baseline: 1.2377x; 1.2377x over previous
#include <cuda_runtime.h>
#include <cuda_fp16.h>
#include <math.h>
#include <stdint.h>

// ---------------- problem constants ----------------
#define BB      2
#define LL      1024
#define DD      768
#define EE      1536
#define NN      16
#define DDELTA  48
#define DCONV   4
#define VV      50280
#define NLAYERS 2
#define ML      (BB*LL)   // 2048 rows
#define PKN     (DDELTA + 2*NN)   // 80 packed rows: [delta1 48 | B 16 | C 16]

// ---------------- scratch (no allocs allowed) ----------------
__device__ float g_resid[BB*LL*DD];
__device__ float g_skip[BB*LL*EE];
__device__ float g_xi  [BB*LL*EE];
__device__ float g_xc  [BB*LL*EE];
__device__ float g_dbc [ML*PKN];          // packed [d1 | B | C] per row
__device__ float g_delta[BB*LL*EE];
__device__ float g_y   [BB*LL*EE];

// fp16 weight / activation copies
__device__ __align__(16) __half h_lm  [VV*DD];
__device__ __align__(16) __half h_skip[NLAYERS*EE*DD];
__device__ __align__(16) __half h_in  [NLAYERS*EE*DD];
__device__ __align__(16) __half h_out [NLAYERS*DD*EE];
__device__ __align__(16) __half h_Wsm [NLAYERS*PKN*EE];   // packed small weights
__device__ __align__(16) __half h_xn  [ML*DD];
__device__ __align__(16) __half h_xc  [ML*EE];
__device__ __align__(16) __half h_y   [ML*EE];

// ---------------- helpers ----------------
__inline__ __device__ float warpReduceSum(float v) {
    #pragma unroll
    for (int o = 16; o > 0; o >>= 1) v += __shfl_down_sync(0xffffffffu, v, o);
    return v;
}

__device__ __forceinline__ uint32_t f2tf32(float f) {
    uint32_t u;
    asm("cvt.rna.tf32.f32 %0, %1;" : "=r"(u) : "f"(f));
    return u;
}

__device__ __forceinline__ void mma_f16(float* c, const uint32_t* a, const uint32_t* b) {
    asm volatile(
        "mma.sync.aligned.m16n8k16.row.col.f32.f16.f16.f32 "
        "{%0,%1,%2,%3}, {%4,%5,%6,%7}, {%8,%9}, {%0,%1,%2,%3};\n"
        : "+f"(c[0]), "+f"(c[1]), "+f"(c[2]), "+f"(c[3])
        : "r"(a[0]), "r"(a[1]), "r"(a[2]), "r"(a[3]), "r"(b[0]), "r"(b[1]));
}

__device__ __forceinline__ void mma_tf32(float* c, const uint32_t* a, const uint32_t* b) {
    asm volatile(
        "mma.sync.aligned.m16n8k8.row.col.f32.tf32.tf32.f32 "
        "{%0,%1,%2,%3}, {%4,%5,%6,%7}, {%8,%9}, {%0,%1,%2,%3};\n"
        : "+f"(c[0]), "+f"(c[1]), "+f"(c[2]), "+f"(c[3])
        : "r"(a[0]), "r"(a[1]), "r"(a[2]), "r"(a[3]), "r"(b[0]), "r"(b[1]));
}

__device__ __forceinline__ void ldsm_x4(uint32_t& r0, uint32_t& r1, uint32_t& r2,
                                        uint32_t& r3, uint32_t saddr) {
    asm volatile("ldmatrix.sync.aligned.m8n8.x4.shared.b16 {%0,%1,%2,%3}, [%4];"
                 : "=r"(r0), "=r"(r1), "=r"(r2), "=r"(r3) : "r"(saddr));
}

__device__ __forceinline__ void cp16(uint32_t dst, const void* src) {
    asm volatile("cp.async.cg.shared.global [%0], [%1], 16;" :: "r"(dst), "l"(src));
}
__device__ __forceinline__ void cp16p(uint32_t dst, const void* src, int sz) {
    asm volatile("cp.async.cg.shared.global [%0], [%1], 16, %2;"
                 :: "r"(dst), "l"(src), "r"(sz));
}
__device__ __forceinline__ void cp_commit() {
    asm volatile("cp.async.commit_group;");
}
template<int NWAIT>
__device__ __forceinline__ void cp_wait() {
    asm volatile("cp.async.wait_group %0;" :: "n"(NWAIT));
}

// ---------------- fp32 -> fp16 convert ----------------
__global__ void f2h_kernel(const float* __restrict__ s, __half* __restrict__ d, int n4) {
    int i = blockIdx.x * blockDim.x + threadIdx.x;
    if (i >= n4) return;
    float4 v = reinterpret_cast<const float4*>(s)[i];
    __half2 h0 = __floats2half2_rn(v.x, v.y);
    __half2 h1 = __floats2half2_rn(v.z, v.w);
    uint2 t;
    t.x = *reinterpret_cast<uint32_t*>(&h0);
    t.y = *reinterpret_cast<uint32_t*>(&h1);
    reinterpret_cast<uint2*>(d)[i] = t;
}

struct F2HJobs {
    const float* s[8];
    __half*      d[8];
    int          n4[8];
};

__global__ void f2h_multi(F2HJobs jobs) {
    int j = blockIdx.y;
    int n4 = jobs.n4[j];
    const float4* s = reinterpret_cast<const float4*>(jobs.s[j]);
    uint2*        d = reinterpret_cast<uint2*>(jobs.d[j]);
    for (int i = blockIdx.x * blockDim.x + threadIdx.x; i < n4;
         i += gridDim.x * blockDim.x) {
        float4 v = s[i];
        __half2 h0 = __floats2half2_rn(v.x, v.y);
        __half2 h1 = __floats2half2_rn(v.z, v.w);
        uint2 t;
        t.x = *reinterpret_cast<uint32_t*>(&h0);
        t.y = *reinterpret_cast<uint32_t*>(&h1);
        d[i] = t;
    }
}

// ================= FP16 HMMA GEMM, 128x128 CTA, 2-stage static smem (PINNED) =================
#define SSH 40                         // halfs per smem row (32 + pad 8)
#define HBUF (128 * SSH * 2)           // bytes per buffer

__device__ __forceinline__ void issue_chunk(uint32_t sAbuf, uint32_t sBbuf,
                                            const __half* __restrict__ Ab,
                                            const __half* __restrict__ Wb,
                                            int K, int k0, int nBase, int N, int tid) {
    #pragma unroll
    for (int f = 0; f < 2; f++) {
        int idx = f * 256 + tid;
        int r = idx >> 2, g = idx & 3;
        cp16(sAbuf + (uint32_t)(r * SSH + g * 8) * 2, Ab + (size_t)r * K + k0 + g * 8);
        int sz = (nBase + r < N) ? 16 : 0;
        cp16p(sBbuf + (uint32_t)(r * SSH + g * 8) * 2, Wb + (size_t)r * K + k0 + g * 8, sz);
    }
}

template<int EPI>
__global__ void __launch_bounds__(256)
gemm_h(const __half* __restrict__ A,
       const __half* __restrict__ W0, const __half* __restrict__ W1,
       float* __restrict__ C0, float* __restrict__ C1,
       int M, int N, int K) {
    __shared__ __half As[2][128][SSH];
    __shared__ __half Bs[2][128][SSH];

    const __half* W = blockIdx.z ? W1 : W0;
    float*        C = blockIdx.z ? C1 : C0;

    const int tid  = threadIdx.x;
    const int lane = tid & 31;
    const int warp = tid >> 5;
    const int wm   = warp >> 2;
    const int wn   = warp & 3;
    const int r    = lane >> 2;
    const int c    = lane & 3;

    const int mBase = blockIdx.y * 128;
    const int nBase = blockIdx.x * 128;
    const int nk = K / 32;
    const __half* Ab = A + (size_t)mBase * K;
    const __half* Wb = W + (size_t)nBase * K;

    const int mat  = lane >> 3;
    const int mrow = lane & 7;
    const int aOff = (((wm * 64) + (mat & 1) * 8 + mrow) * SSH + ((mat >> 1) * 8)) * 2;
    const int bOff = (((wn * 32) + (mat >> 1) * 8 + mrow) * SSH + ((mat & 1) * 8)) * 2;
    const uint32_t sA = (uint32_t)__cvta_generic_to_shared(&As[0][0][0]);
    const uint32_t sB = (uint32_t)__cvta_generic_to_shared(&Bs[0][0][0]);

    float acc[4][4][4];
    #pragma unroll
    for (int i = 0; i < 4; i++)
        #pragma unroll
        for (int j = 0; j < 4; j++)
            #pragma unroll
            for (int k = 0; k < 4; k++) acc[i][j][k] = 0.f;

    issue_chunk(sA, sB, Ab, Wb, K, 0, nBase, N, tid);
    cp_commit();
    if (nk > 1) {
        issue_chunk(sA + HBUF, sB + HBUF, Ab, Wb, K, 32, nBase, N, tid);
        cp_commit();
    }

    for (int ch = 0; ch < nk; ch++) {
        if (ch + 1 < nk) cp_wait<1>(); else cp_wait<0>();
        __syncthreads();

        const uint32_t aBase = sA + (ch & 1) * HBUF + aOff;
        const uint32_t bBase = sB + (ch & 1) * HBUF + bOff;
        #pragma unroll
        for (int ks = 0; ks < 32; ks += 16) {
            uint32_t af[4][4], bf[4][2];
            #pragma unroll
            for (int mt = 0; mt < 4; mt++)
                ldsm_x4(af[mt][0], af[mt][1], af[mt][2], af[mt][3],
                        aBase + (uint32_t)(mt * 16 * SSH + ks) * 2);
            #pragma unroll
            for (int np = 0; np < 2; np++)
                ldsm_x4(bf[2*np][0], bf[2*np][1], bf[2*np+1][0], bf[2*np+1][1],
                        bBase + (uint32_t)(np * 16 * SSH + ks) * 2);
            #pragma unroll
            for (int mt = 0; mt < 4; mt++)
                #pragma unroll
                for (int nt = 0; nt < 4; nt++)
                    mma_f16(acc[mt][nt], af[mt], bf[nt]);
        }
        __syncthreads();

        if (ch + 2 < nk) {
            issue_chunk(sA + (ch & 1) * HBUF, sB + (ch & 1) * HBUF,
                        Ab, Wb, K, (ch + 2) * 32, nBase, N, tid);
            cp_commit();
        }
    }

    #pragma unroll
    for (int mt = 0; mt < 4; mt++) {
        #pragma unroll
        for (int nt = 0; nt < 4; nt++) {
            int mg0 = mBase + wm * 64 + mt * 16 + r;
            int ng0 = nBase + wn * 32 + nt * 8 + 2 * c;
            #pragma unroll
            for (int ri = 0; ri < 2; ri++) {
                #pragma unroll
                for (int ci = 0; ci < 2; ci++) {
                    int m = mg0 + ri * 8;
                    int n = ng0 + ci;
                    float v = acc[mt][nt][ri * 2 + ci];
                    if (n < N) {
                        size_t idx = (size_t)m * N + n;
                        if (EPI == 1) C[idx] += v; else C[idx] = v;
                    }
                }
            }
        }
    }
}

// ---------------- TF32 GEMM with softplus epilogue (K=48 path, strided A) ----------------
#define SST 20
__global__ void __launch_bounds__(256)
gemm_tf32_sp(const float* __restrict__ A, int lda,
             const float* __restrict__ W,
             const float* __restrict__ bias, float* __restrict__ C,
             int M, int N, int K) {
    __shared__ uint32_t As[2][128][SST];
    __shared__ uint32_t Bs[2][128][SST];

    const int tid  = threadIdx.x;
    const int lane = tid & 31;
    const int warp = tid >> 5;
    const int wm   = warp >> 2;
    const int wn   = warp & 3;
    const int r    = lane >> 2;
    const int c    = lane & 3;

    const int ldRow = tid >> 2;
    const int ldCol = (tid & 3) * 4;

    const int mBase = blockIdx.y * 128;
    const int nBase = blockIdx.x * 128;
    const int nk = K / 16;

    const int mat = lane >> 3;
    const int mrow = lane & 7;
    const int aOff = (((wm * 64) + (mat & 1) * 8 + mrow) * SST + ((mat >> 1) * 4)) * 4;
    const int bOff = (((wn * 32) + (mat >> 1) * 8 + mrow) * SST + ((mat & 1) * 4)) * 4;
    const uint32_t sA = (uint32_t)__cvta_generic_to_shared(&As[0][0][0]);
    const uint32_t sB = (uint32_t)__cvta_generic_to_shared(&Bs[0][0][0]);
    const int BUF = 128 * SST * 4;

    float acc[4][4][4];
    #pragma unroll
    for (int i = 0; i < 4; i++)
        #pragma unroll
        for (int j = 0; j < 4; j++)
            #pragma unroll
            for (int k = 0; k < 4; k++) acc[i][j][k] = 0.f;

    float4 a0p, a1p, w0p, w1p;
    {
        const float* ap = A + (size_t)(mBase + ldRow) * lda + ldCol;
        a0p = *reinterpret_cast<const float4*>(ap);
        a1p = *reinterpret_cast<const float4*>(ap + (size_t)64 * lda);
        int n0 = nBase + ldRow, n1 = n0 + 64;
        w0p = make_float4(0.f,0.f,0.f,0.f);
        w1p = w0p;
        if (n0 < N) w0p = *reinterpret_cast<const float4*>(W + (size_t)n0 * K + ldCol);
        if (n1 < N) w1p = *reinterpret_cast<const float4*>(W + (size_t)n1 * K + ldCol);
    }
    {
        uint4 t;
        t.x=f2tf32(a0p.x); t.y=f2tf32(a0p.y); t.z=f2tf32(a0p.z); t.w=f2tf32(a0p.w);
        *reinterpret_cast<uint4*>(&As[0][ldRow][ldCol]) = t;
        t.x=f2tf32(a1p.x); t.y=f2tf32(a1p.y); t.z=f2tf32(a1p.z); t.w=f2tf32(a1p.w);
        *reinterpret_cast<uint4*>(&As[0][ldRow+64][ldCol]) = t;
        t.x=f2tf32(w0p.x); t.y=f2tf32(w0p.y); t.z=f2tf32(w0p.z); t.w=f2tf32(w0p.w);
        *reinterpret_cast<uint4*>(&Bs[0][ldRow][ldCol]) = t;
        t.x=f2tf32(w1p.x); t.y=f2tf32(w1p.y); t.z=f2tf32(w1p.z); t.w=f2tf32(w1p.w);
        *reinterpret_cast<uint4*>(&Bs[0][ldRow+64][ldCol]) = t;
    }
    __syncthreads();

    int cur = 0;
    for (int ch = 0; ch < nk; ch++) {
        if (ch + 1 < nk) {
            int k0 = (ch + 1) * 16;
            const float* ap = A + (size_t)(mBase + ldRow) * lda + k0 + ldCol;
            a0p = *reinterpret_cast<const float4*>(ap);
            a1p = *reinterpret_cast<const float4*>(ap + (size_t)64 * lda);
            int n0 = nBase + ldRow, n1 = n0 + 64;
            w0p = make_float4(0.f,0.f,0.f,0.f);
            w1p = w0p;
            if (n0 < N) w0p = *reinterpret_cast<const float4*>(W + (size_t)n0 * K + k0 + ldCol);
            if (n1 < N) w1p = *reinterpret_cast<const float4*>(W + (size_t)n1 * K + k0 + ldCol);
        }

        const uint32_t aBase = sA + cur * BUF + aOff;
        const uint32_t bBase = sB + cur * BUF + bOff;
        #pragma unroll
        for (int ks = 0; ks < 16; ks += 8) {
            uint32_t af[4][4], bf[4][2];
            #pragma unroll
            for (int mt = 0; mt < 4; mt++)
                ldsm_x4(af[mt][0], af[mt][1], af[mt][2], af[mt][3],
                        aBase + (mt * 16 * SST + ks) * 4);
            #pragma unroll
            for (int np = 0; np < 2; np++)
                ldsm_x4(bf[2*np][0], bf[2*np][1], bf[2*np+1][0], bf[2*np+1][1],
                        bBase + (np * 16 * SST + ks) * 4);
            #pragma unroll
            for (int mt = 0; mt < 4; mt++)
                #pragma unroll
                for (int nt = 0; nt < 4; nt++)
                    mma_tf32(acc[mt][nt], af[mt], bf[nt]);
        }

        if (ch + 1 < nk) {
            int nxt = cur ^ 1;
            uint4 t;
            t.x=f2tf32(a0p.x); t.y=f2tf32(a0p.y); t.z=f2tf32(a0p.z); t.w=f2tf32(a0p.w);
            *reinterpret_cast<uint4*>(&As[nxt][ldRow][ldCol]) = t;
            t.x=f2tf32(a1p.x); t.y=f2tf32(a1p.y); t.z=f2tf32(a1p.z); t.w=f2tf32(a1p.w);
            *reinterpret_cast<uint4*>(&As[nxt][ldRow+64][ldCol]) = t;
            t.x=f2tf32(w0p.x); t.y=f2tf32(w0p.y); t.z=f2tf32(w0p.z); t.w=f2tf32(w0p.w);
            *reinterpret_cast<uint4*>(&Bs[nxt][ldRow][ldCol]) = t;
            t.x=f2tf32(w1p.x); t.y=f2tf32(w1p.y); t.z=f2tf32(w1p.z); t.w=f2tf32(w1p.w);
            *reinterpret_cast<uint4*>(&Bs[nxt][ldRow+64][ldCol]) = t;
        }
        __syncthreads();
        cur ^= 1;
    }

    #pragma unroll
    for (int mt = 0; mt < 4; mt++) {
        #pragma unroll
        for (int nt = 0; nt < 4; nt++) {
            int mg0 = mBase + wm * 64 + mt * 16 + r;
            int ng0 = nBase + wn * 32 + nt * 8 + 2 * c;
            #pragma unroll
            for (int ri = 0; ri < 2; ri++) {
                #pragma unroll
                for (int ci = 0; ci < 2; ci++) {
                    int m = mg0 + ri * 8;
                    int n = ng0 + ci;
                    if (n < N) {
                        float s = acc[mt][nt][ri * 2 + ci] + bias[n];
                        C[(size_t)m * N + n] = (s > 20.f) ? s : log1pf(expf(s));
                    }
                }
            }
        }
    }
}

// ---------------- embedding gather (float4 vectorized) ----------------
__global__ void embed_kernel(const int* __restrict__ tokens,
                             const float* __restrict__ emb,
                             float* __restrict__ resid) {
    int row = blockIdx.x;
    int t = tokens[row];
    const float4* src = reinterpret_cast<const float4*>(emb + (size_t)t * DD);
    float4* dst = reinterpret_cast<float4*>(resid + (size_t)row * DD);
    for (int i = threadIdx.x; i < DD / 4; i += blockDim.x) dst[i] = src[i];
}

// ---------------- rmsnorm -> fp16 output ----------------
__global__ void rmsnorm_h_kernel(const float* __restrict__ x,
                                 const float* __restrict__ w,
                                 __half* __restrict__ out) {
    int row = blockIdx.x;
    const float* xr = x + (size_t)row * DD;
    float s = 0.f;
    for (int i = threadIdx.x; i < DD; i += 256) { float v = xr[i]; s = fmaf(v, v, s); }
    s = warpReduceSum(s);
    __shared__ float red[8];
    int warp = threadIdx.x >> 5, lane = threadIdx.x & 31;
    if (lane == 0) red[warp] = s;
    __syncthreads();
    if (warp == 0) {
        float v = (lane < 8) ? red[lane] : 0.f;
        v = warpReduceSum(v);
        if (lane == 0) red[0] = rsqrtf(v / (float)DD + 1e-5f);
    }
    __syncthreads();
    float scale = red[0];
    __half* o = out + (size_t)row * DD;
    for (int i = threadIdx.x; i < DD; i += 256)
        o[i] = __float2half_rn(xr[i] * scale * w[i]);
}

// ---------------- depthwise causal conv1d + bias + silu (fp32 + fp16 out) ----------------
__global__ void conv_silu_kernel(const float* __restrict__ xi,
                                 const float* __restrict__ cw,
                                 const float* __restrict__ cb,
                                 float* __restrict__ out,
                                 __half* __restrict__ outh) {
    int idx = blockIdx.x * blockDim.x + threadIdx.x;
    if (idx >= BB * LL * EE) return;
    int e  = idx % EE;
    int bl = idx / EE;
    int l  = bl % LL;
    float acc = cb[e];
    #pragma unroll
    for (int k = 0; k < DCONV; k++) {
        int ls = l - (DCONV - 1) + k;
        if (ls >= 0)
            acc = fmaf(cw[e * DCONV + k],
                       xi[(size_t)(bl - (DCONV - 1) + k) * EE + e], acc);
    }
    float v = acc / (1.f + __expf(-acc));
    out[idx] = v;
    outh[idx] = __float2half_rn(v);
}

// ---------------- selective scan: 4 threads per channel (4 states each) ----------------
// grid = BB*EE*4/256 = 48 CTAs. Quad (tid&3) = state group; shfl-reduce y over quad.
__global__ void __launch_bounds__(256)
scan_kernel(const float* __restrict__ delta, const float* __restrict__ x,
            const float* __restrict__ Bm, const float* __restrict__ Cm, int ldbc,
            const float* __restrict__ A_log, float* __restrict__ y) {
    int ch = blockIdx.x * 64 + (threadIdx.x >> 2);   // 0 .. BB*EE-1
    int ng = threadIdx.x & 3;                         // state group 0..3
    int b  = ch / EE;
    int e  = ch % EE;

    float a[4], h[4];
    #pragma unroll
    for (int j = 0; j < 4; j++) {
        a[j] = -expf(A_log[e * NN + ng * 4 + j]);
        h[j] = 0.f;
    }

    const size_t row0 = (size_t)b * LL;
    #pragma unroll 2
    for (int l = 0; l < LL; l++) {
        size_t row = row0 + l;
        float d  = delta[row * EE + e];
        float xv = x    [row * EE + e];
        float dx = d * xv;
        float4 Bv = *reinterpret_cast<const float4*>(Bm + row * ldbc + ng * 4);
        float4 Cv = *reinterpret_cast<const float4*>(Cm + row * ldbc + ng * 4);
        float yacc;
        h[0] = __expf(d * a[0]) * h[0] + dx * Bv.x;
        h[1] = __expf(d * a[1]) * h[1] + dx * Bv.y;
        h[2] = __expf(d * a[2]) * h[2] + dx * Bv.z;
        h[3] = __expf(d * a[3]) * h[3] + dx * Bv.w;
        yacc = h[0] * Cv.x;
        yacc = fmaf(h[1], Cv.y, yacc);
        yacc = fmaf(h[2], Cv.z, yacc);
        yacc = fmaf(h[3], Cv.w, yacc);
        yacc += __shfl_xor_sync(0xffffffffu, yacc, 1);
        yacc += __shfl_xor_sync(0xffffffffu, yacc, 2);
        if (ng == 0) y[row * EE + e] = yacc;
    }
}

// ---------------- output gating -> fp16 y ----------------
__global__ void combine_kernel(const float* __restrict__ y,
                               const float* __restrict__ xc,
                               const float* __restrict__ wD,
                               const float* __restrict__ skip,
                               __half* __restrict__ yh) {
    int idx = blockIdx.x * blockDim.x + threadIdx.x;
    if (idx >= BB * LL * EE) return;
    int e = idx % EE;
    float v  = fmaf(xc[idx], wD[e], y[idx]);
    float sk = skip[idx];
    yh[idx] = __float2half_rn(v * (sk / (1.f + __expf(-sk))));
}

// ---------------- launch ----------------
extern "C" void kernel_launch(void* const* d_in, const int* in_sizes, int n_in,
                              void* d_out, int out_size) {
    (void)in_sizes; (void)n_in; (void)out_size;

    const int*   tokens = (const int*)  d_in[0];
    const float* emb    = (const float*)d_in[1];
    const float* norm_w = (const float*)d_in[2];
    const float* skip_w = (const float*)d_in[3];
    const float* in_w   = (const float*)d_in[4];
    const float* conv_w = (const float*)d_in[5];
    const float* conv_b = (const float*)d_in[6];
    const float* Wd1    = (const float*)d_in[7];
    const float* Wd2_w  = (const float*)d_in[8];
    const float* Wd2_b  = (const float*)d_in[9];
    const float* WB     = (const float*)d_in[10];
    const float* WC     = (const float*)d_in[11];
    const float* A_log  = (const float*)d_in[12];
    const float* W_D    = (const float*)d_in[13];
    const float* out_w  = (const float*)d_in[14];
    const float* fnw    = (const float*)d_in[15];
    const float* lm     = (const float*)d_in[16];
    float* out = (float*)d_out;

    float *resid, *skip, *xi, *xc, *dbc, *delta, *y;
    cudaGetSymbolAddress((void**)&resid, g_resid);
    cudaGetSymbolAddress((void**)&skip,  g_skip);
    cudaGetSymbolAddress((void**)&xi,    g_xi);
    cudaGetSymbolAddress((void**)&xc,    g_xc);
    cudaGetSymbolAddress((void**)&dbc,   g_dbc);
    cudaGetSymbolAddress((void**)&delta, g_delta);
    cudaGetSymbolAddress((void**)&y,     g_y);

    __half *hlm, *hskip, *hin, *hout, *hWsm, *hxn, *hxc, *hy;
    cudaGetSymbolAddress((void**)&hlm,   h_lm);
    cudaGetSymbolAddress((void**)&hskip, h_skip);
    cudaGetSymbolAddress((void**)&hin,   h_in);
    cudaGetSymbolAddress((void**)&hout,  h_out);
    cudaGetSymbolAddress((void**)&hWsm,  h_Wsm);
    cudaGetSymbolAddress((void**)&hxn,   h_xn);
    cudaGetSymbolAddress((void**)&hxc,   h_xc);
    cudaGetSymbolAddress((void**)&hy,    h_y);

    // ---- weight conversions: 3 launches total ----
    {
        int n4 = VV * DD / 4;
        f2h_kernel<<<(n4 + 255) / 256, 256>>>(lm, hlm, n4);

        F2HJobs jb = {};
        jb.s[0] = skip_w; jb.d[0] = hskip; jb.n4[0] = NLAYERS * EE * DD / 4;
        jb.s[1] = in_w;   jb.d[1] = hin;   jb.n4[1] = NLAYERS * EE * DD / 4;
        f2h_multi<<<dim3(2304, 2, 1), 256>>>(jb);

        F2HJobs jc = {};
        jc.s[0] = out_w; jc.d[0] = hout; jc.n4[0] = NLAYERS * DD * EE / 4;
        int j = 1;
        for (int l = 0; l < NLAYERS; l++) {
            jc.s[j] = Wd1 + (size_t)l * DDELTA * EE;
            jc.d[j] = hWsm + (size_t)l * PKN * EE;
            jc.n4[j] = DDELTA * EE / 4; j++;
            jc.s[j] = WB + (size_t)l * NN * EE;
            jc.d[j] = hWsm + (size_t)l * PKN * EE + (size_t)DDELTA * EE;
            jc.n4[j] = NN * EE / 4; j++;
            jc.s[j] = WC + (size_t)l * NN * EE;
            jc.d[j] = hWsm + (size_t)l * PKN * EE + (size_t)(DDELTA + NN) * EE;
            jc.n4[j] = NN * EE / 4; j++;
        }
        f2h_multi<<<dim3(2304, 7, 1), 256>>>(jc);
    }

    const int totE = BB * LL * EE;
    const dim3 gE2((EE  + 127) / 128, ML / 128, 2);  // skip + in fused
    const dim3 gP ((PKN + 127) / 128, ML / 128, 1);  // packed d1|B|C
    const dim3 gDe((EE  + 127) / 128, ML / 128, 1);  // tf32 softplus
    const dim3 gO ((DD  + 127) / 128, ML / 128, 1);
    const dim3 gV ((VV  + 127) / 128, ML / 128, 1);

    embed_kernel<<<ML, 256>>>(tokens, emb, resid);

    for (int lyr = 0; lyr < NLAYERS; ++lyr) {
        rmsnorm_h_kernel<<<ML, 256>>>(resid, norm_w + lyr * DD, hxn);

        gemm_h<0><<<gE2, 256>>>(hxn,
            hskip + (size_t)lyr * EE * DD, hin + (size_t)lyr * EE * DD,
            skip, xi, ML, EE, DD);

        conv_silu_kernel<<<(totE + 255) / 256, 256>>>(xi, conv_w + lyr * EE * DCONV,
                                                      conv_b + lyr * EE, xc, hxc);

        // packed small GEMM: [d1 48 | B 16 | C 16] = xc @ Wsm^T
        gemm_h<0><<<gP, 256>>>(hxc, hWsm + (size_t)lyr * PKN * EE, nullptr,
                               dbc, nullptr, ML, PKN, EE);

        gemm_tf32_sp<<<gDe, 256>>>(dbc, PKN, Wd2_w + (size_t)lyr * EE * DDELTA,
                                   Wd2_b + lyr * EE, delta, ML, EE, DDELTA);

        scan_kernel<<<BB * EE * 4 / 256, 256>>>(delta, xc,
                                                dbc + DDELTA, dbc + DDELTA + NN, PKN,
                                                A_log + lyr * EE * NN, y);

        combine_kernel<<<(totE + 255) / 256, 256>>>(y, xc, W_D + lyr * EE, skip, hy);

        gemm_h<1><<<gO, 256>>>(hy, hout + (size_t)lyr * DD * EE, nullptr,
                               resid, nullptr, ML, DD, EE);
    }

    rmsnorm_h_kernel<<<ML, 256>>>(resid, fnw, hxn);
    gemm_h<0><<<gV, 256>>>(hxn, hlm, nullptr, out, nullptr, ML, VV, DD);
}

// round 14
// speedup vs baseline: 1.2626x; 1.0201x over previous
#include <cuda_runtime.h>
#include <cuda_fp16.h>
#include <math.h>
#include <stdint.h>

// ---------------- problem constants ----------------
#define BB      2
#define LL      1024
#define DD      768
#define EE      1536
#define NN      16
#define DDELTA  48
#define DCONV   4
#define VV      50280
#define NLAYERS 2
#define ML      (BB*LL)   // 2048 rows
#define PKN     (DDELTA + 2*NN)   // 80 packed rows: [delta1 48 | B 16 | C 16]

// ---------------- scratch (no allocs allowed) ----------------
__device__ float g_resid[BB*LL*DD];
__device__ float g_skip[BB*LL*EE];
__device__ float g_xi  [BB*LL*EE];
__device__ float g_xc  [BB*LL*EE];
__device__ float g_dbc [ML*PKN];          // packed [d1 | B | C] per row
__device__ float g_delta[BB*LL*EE];
__device__ float g_y   [BB*LL*EE];

// fp16 weight / activation copies
__device__ __align__(16) __half h_lm  [VV*DD];
__device__ __align__(16) __half h_skip[NLAYERS*EE*DD];
__device__ __align__(16) __half h_in  [NLAYERS*EE*DD];
__device__ __align__(16) __half h_out [NLAYERS*DD*EE];
__device__ __align__(16) __half h_Wsm [NLAYERS*PKN*EE];   // packed small weights
__device__ __align__(16) __half h_xn  [ML*DD];
__device__ __align__(16) __half h_xc  [ML*EE];
__device__ __align__(16) __half h_y   [ML*EE];

// ---------------- helpers ----------------
__inline__ __device__ float warpReduceSum(float v) {
    #pragma unroll
    for (int o = 16; o > 0; o >>= 1) v += __shfl_down_sync(0xffffffffu, v, o);
    return v;
}

__device__ __forceinline__ uint32_t f2tf32(float f) {
    uint32_t u;
    asm("cvt.rna.tf32.f32 %0, %1;" : "=r"(u) : "f"(f));
    return u;
}

__device__ __forceinline__ void mma_f16(float* c, const uint32_t* a, const uint32_t* b) {
    asm volatile(
        "mma.sync.aligned.m16n8k16.row.col.f32.f16.f16.f32 "
        "{%0,%1,%2,%3}, {%4,%5,%6,%7}, {%8,%9}, {%0,%1,%2,%3};\n"
        : "+f"(c[0]), "+f"(c[1]), "+f"(c[2]), "+f"(c[3])
        : "r"(a[0]), "r"(a[1]), "r"(a[2]), "r"(a[3]), "r"(b[0]), "r"(b[1]));
}

__device__ __forceinline__ void mma_tf32(float* c, const uint32_t* a, const uint32_t* b) {
    asm volatile(
        "mma.sync.aligned.m16n8k8.row.col.f32.tf32.tf32.f32 "
        "{%0,%1,%2,%3}, {%4,%5,%6,%7}, {%8,%9}, {%0,%1,%2,%3};\n"
        : "+f"(c[0]), "+f"(c[1]), "+f"(c[2]), "+f"(c[3])
        : "r"(a[0]), "r"(a[1]), "r"(a[2]), "r"(a[3]), "r"(b[0]), "r"(b[1]));
}

__device__ __forceinline__ void ldsm_x4(uint32_t& r0, uint32_t& r1, uint32_t& r2,
                                        uint32_t& r3, uint32_t saddr) {
    asm volatile("ldmatrix.sync.aligned.m8n8.x4.shared.b16 {%0,%1,%2,%3}, [%4];"
                 : "=r"(r0), "=r"(r1), "=r"(r2), "=r"(r3) : "r"(saddr));
}

__device__ __forceinline__ void cp16(uint32_t dst, const void* src) {
    asm volatile("cp.async.cg.shared.global [%0], [%1], 16;" :: "r"(dst), "l"(src));
}
__device__ __forceinline__ void cp16p(uint32_t dst, const void* src, int sz) {
    asm volatile("cp.async.cg.shared.global [%0], [%1], 16, %2;"
                 :: "r"(dst), "l"(src), "r"(sz));
}
__device__ __forceinline__ void cp_commit() {
    asm volatile("cp.async.commit_group;");
}
template<int NWAIT>
__device__ __forceinline__ void cp_wait() {
    asm volatile("cp.async.wait_group %0;" :: "n"(NWAIT));
}

// ---------------- fp32 -> fp16 convert: single launch, 10 jobs ----------------
struct F2HJobs {
    const float* s[12];
    __half*      d[12];
    int          n4[12];
};

__global__ void f2h_multi(F2HJobs jobs) {
    int j = blockIdx.y;
    int n4 = jobs.n4[j];
    const float4* s = reinterpret_cast<const float4*>(jobs.s[j]);
    uint2*        d = reinterpret_cast<uint2*>(jobs.d[j]);
    for (int i = blockIdx.x * blockDim.x + threadIdx.x; i < n4;
         i += gridDim.x * blockDim.x) {
        float4 v = s[i];
        __half2 h0 = __floats2half2_rn(v.x, v.y);
        __half2 h1 = __floats2half2_rn(v.z, v.w);
        uint2 t;
        t.x = *reinterpret_cast<uint32_t*>(&h0);
        t.y = *reinterpret_cast<uint32_t*>(&h1);
        d[i] = t;
    }
}

// ================= FP16 HMMA GEMM, 128x128 CTA, 2-stage static smem (PINNED) =================
#define SSH 40                         // halfs per smem row (32 + pad 8)
#define HBUF (128 * SSH * 2)           // bytes per buffer

__device__ __forceinline__ void issue_chunk(uint32_t sAbuf, uint32_t sBbuf,
                                            const __half* __restrict__ Ab,
                                            const __half* __restrict__ Wb,
                                            int K, int k0, int nBase, int N, int tid) {
    #pragma unroll
    for (int f = 0; f < 2; f++) {
        int idx = f * 256 + tid;
        int r = idx >> 2, g = idx & 3;
        cp16(sAbuf + (uint32_t)(r * SSH + g * 8) * 2, Ab + (size_t)r * K + k0 + g * 8);
        int sz = (nBase + r < N) ? 16 : 0;
        cp16p(sBbuf + (uint32_t)(r * SSH + g * 8) * 2, Wb + (size_t)r * K + k0 + g * 8, sz);
    }
}

template<int EPI>
__global__ void __launch_bounds__(256)
gemm_h(const __half* __restrict__ A,
       const __half* __restrict__ W0, const __half* __restrict__ W1,
       float* __restrict__ C0, float* __restrict__ C1,
       int M, int N, int K) {
    __shared__ __half As[2][128][SSH];
    __shared__ __half Bs[2][128][SSH];

    const __half* W = blockIdx.z ? W1 : W0;
    float*        C = blockIdx.z ? C1 : C0;

    const int tid  = threadIdx.x;
    const int lane = tid & 31;
    const int warp = tid >> 5;
    const int wm   = warp >> 2;
    const int wn   = warp & 3;
    const int r    = lane >> 2;
    const int c    = lane & 3;

    const int mBase = blockIdx.y * 128;
    const int nBase = blockIdx.x * 128;
    const int nk = K / 32;
    const __half* Ab = A + (size_t)mBase * K;
    const __half* Wb = W + (size_t)nBase * K;

    const int mat  = lane >> 3;
    const int mrow = lane & 7;
    const int aOff = (((wm * 64) + (mat & 1) * 8 + mrow) * SSH + ((mat >> 1) * 8)) * 2;
    const int bOff = (((wn * 32) + (mat >> 1) * 8 + mrow) * SSH + ((mat & 1) * 8)) * 2;
    const uint32_t sA = (uint32_t)__cvta_generic_to_shared(&As[0][0][0]);
    const uint32_t sB = (uint32_t)__cvta_generic_to_shared(&Bs[0][0][0]);

    float acc[4][4][4];
    #pragma unroll
    for (int i = 0; i < 4; i++)
        #pragma unroll
        for (int j = 0; j < 4; j++)
            #pragma unroll
            for (int k = 0; k < 4; k++) acc[i][j][k] = 0.f;

    issue_chunk(sA, sB, Ab, Wb, K, 0, nBase, N, tid);
    cp_commit();
    if (nk > 1) {
        issue_chunk(sA + HBUF, sB + HBUF, Ab, Wb, K, 32, nBase, N, tid);
        cp_commit();
    }

    for (int ch = 0; ch < nk; ch++) {
        if (ch + 1 < nk) cp_wait<1>(); else cp_wait<0>();
        __syncthreads();

        const uint32_t aBase = sA + (ch & 1) * HBUF + aOff;
        const uint32_t bBase = sB + (ch & 1) * HBUF + bOff;
        #pragma unroll
        for (int ks = 0; ks < 32; ks += 16) {
            uint32_t af[4][4], bf[4][2];
            #pragma unroll
            for (int mt = 0; mt < 4; mt++)
                ldsm_x4(af[mt][0], af[mt][1], af[mt][2], af[mt][3],
                        aBase + (uint32_t)(mt * 16 * SSH + ks) * 2);
            #pragma unroll
            for (int np = 0; np < 2; np++)
                ldsm_x4(bf[2*np][0], bf[2*np][1], bf[2*np+1][0], bf[2*np+1][1],
                        bBase + (uint32_t)(np * 16 * SSH + ks) * 2);
            #pragma unroll
            for (int mt = 0; mt < 4; mt++)
                #pragma unroll
                for (int nt = 0; nt < 4; nt++)
                    mma_f16(acc[mt][nt], af[mt], bf[nt]);
        }
        __syncthreads();

        if (ch + 2 < nk) {
            issue_chunk(sA + (ch & 1) * HBUF, sB + (ch & 1) * HBUF,
                        Ab, Wb, K, (ch + 2) * 32, nBase, N, tid);
            cp_commit();
        }
    }

    #pragma unroll
    for (int mt = 0; mt < 4; mt++) {
        #pragma unroll
        for (int nt = 0; nt < 4; nt++) {
            int mg0 = mBase + wm * 64 + mt * 16 + r;
            int ng0 = nBase + wn * 32 + nt * 8 + 2 * c;
            #pragma unroll
            for (int ri = 0; ri < 2; ri++) {
                #pragma unroll
                for (int ci = 0; ci < 2; ci++) {
                    int m = mg0 + ri * 8;
                    int n = ng0 + ci;
                    float v = acc[mt][nt][ri * 2 + ci];
                    if (n < N) {
                        size_t idx = (size_t)m * N + n;
                        if (EPI == 1) C[idx] += v; else C[idx] = v;
                    }
                }
            }
        }
    }
}

// ---------------- TF32 GEMM with softplus epilogue (K=48 path, strided A) ----------------
#define SST 20
__global__ void __launch_bounds__(256)
gemm_tf32_sp(const float* __restrict__ A, int lda,
             const float* __restrict__ W,
             const float* __restrict__ bias, float* __restrict__ C,
             int M, int N, int K) {
    __shared__ uint32_t As[2][128][SST];
    __shared__ uint32_t Bs[2][128][SST];

    const int tid  = threadIdx.x;
    const int lane = tid & 31;
    const int warp = tid >> 5;
    const int wm   = warp >> 2;
    const int wn   = warp & 3;
    const int r    = lane >> 2;
    const int c    = lane & 3;

    const int ldRow = tid >> 2;
    const int ldCol = (tid & 3) * 4;

    const int mBase = blockIdx.y * 128;
    const int nBase = blockIdx.x * 128;
    const int nk = K / 16;

    const int mat = lane >> 3;
    const int mrow = lane & 7;
    const int aOff = (((wm * 64) + (mat & 1) * 8 + mrow) * SST + ((mat >> 1) * 4)) * 4;
    const int bOff = (((wn * 32) + (mat >> 1) * 8 + mrow) * SST + ((mat & 1) * 4)) * 4;
    const uint32_t sA = (uint32_t)__cvta_generic_to_shared(&As[0][0][0]);
    const uint32_t sB = (uint32_t)__cvta_generic_to_shared(&Bs[0][0][0]);
    const int BUF = 128 * SST * 4;

    float acc[4][4][4];
    #pragma unroll
    for (int i = 0; i < 4; i++)
        #pragma unroll
        for (int j = 0; j < 4; j++)
            #pragma unroll
            for (int k = 0; k < 4; k++) acc[i][j][k] = 0.f;

    float4 a0p, a1p, w0p, w1p;
    {
        const float* ap = A + (size_t)(mBase + ldRow) * lda + ldCol;
        a0p = *reinterpret_cast<const float4*>(ap);
        a1p = *reinterpret_cast<const float4*>(ap + (size_t)64 * lda);
        int n0 = nBase + ldRow, n1 = n0 + 64;
        w0p = make_float4(0.f,0.f,0.f,0.f);
        w1p = w0p;
        if (n0 < N) w0p = *reinterpret_cast<const float4*>(W + (size_t)n0 * K + ldCol);
        if (n1 < N) w1p = *reinterpret_cast<const float4*>(W + (size_t)n1 * K + ldCol);
    }
    {
        uint4 t;
        t.x=f2tf32(a0p.x); t.y=f2tf32(a0p.y); t.z=f2tf32(a0p.z); t.w=f2tf32(a0p.w);
        *reinterpret_cast<uint4*>(&As[0][ldRow][ldCol]) = t;
        t.x=f2tf32(a1p.x); t.y=f2tf32(a1p.y); t.z=f2tf32(a1p.z); t.w=f2tf32(a1p.w);
        *reinterpret_cast<uint4*>(&As[0][ldRow+64][ldCol]) = t;
        t.x=f2tf32(w0p.x); t.y=f2tf32(w0p.y); t.z=f2tf32(w0p.z); t.w=f2tf32(w0p.w);
        *reinterpret_cast<uint4*>(&Bs[0][ldRow][ldCol]) = t;
        t.x=f2tf32(w1p.x); t.y=f2tf32(w1p.y); t.z=f2tf32(w1p.z); t.w=f2tf32(w1p.w);
        *reinterpret_cast<uint4*>(&Bs[0][ldRow+64][ldCol]) = t;
    }
    __syncthreads();

    int cur = 0;
    for (int ch = 0; ch < nk; ch++) {
        if (ch + 1 < nk) {
            int k0 = (ch + 1) * 16;
            const float* ap = A + (size_t)(mBase + ldRow) * lda + k0 + ldCol;
            a0p = *reinterpret_cast<const float4*>(ap);
            a1p = *reinterpret_cast<const float4*>(ap + (size_t)64 * lda);
            int n0 = nBase + ldRow, n1 = n0 + 64;
            w0p = make_float4(0.f,0.f,0.f,0.f);
            w1p = w0p;
            if (n0 < N) w0p = *reinterpret_cast<const float4*>(W + (size_t)n0 * K + k0 + ldCol);
            if (n1 < N) w1p = *reinterpret_cast<const float4*>(W + (size_t)n1 * K + k0 + ldCol);
        }

        const uint32_t aBase = sA + cur * BUF + aOff;
        const uint32_t bBase = sB + cur * BUF + bOff;
        #pragma unroll
        for (int ks = 0; ks < 16; ks += 8) {
            uint32_t af[4][4], bf[4][2];
            #pragma unroll
            for (int mt = 0; mt < 4; mt++)
                ldsm_x4(af[mt][0], af[mt][1], af[mt][2], af[mt][3],
                        aBase + (mt * 16 * SST + ks) * 4);
            #pragma unroll
            for (int np = 0; np < 2; np++)
                ldsm_x4(bf[2*np][0], bf[2*np][1], bf[2*np+1][0], bf[2*np+1][1],
                        bBase + (np * 16 * SST + ks) * 4);
            #pragma unroll
            for (int mt = 0; mt < 4; mt++)
                #pragma unroll
                for (int nt = 0; nt < 4; nt++)
                    mma_tf32(acc[mt][nt], af[mt], bf[nt]);
        }

        if (ch + 1 < nk) {
            int nxt = cur ^ 1;
            uint4 t;
            t.x=f2tf32(a0p.x); t.y=f2tf32(a0p.y); t.z=f2tf32(a0p.z); t.w=f2tf32(a0p.w);
            *reinterpret_cast<uint4*>(&As[nxt][ldRow][ldCol]) = t;
            t.x=f2tf32(a1p.x); t.y=f2tf32(a1p.y); t.z=f2tf32(a1p.z); t.w=f2tf32(a1p.w);
            *reinterpret_cast<uint4*>(&As[nxt][ldRow+64][ldCol]) = t;
            t.x=f2tf32(w0p.x); t.y=f2tf32(w0p.y); t.z=f2tf32(w0p.z); t.w=f2tf32(w0p.w);
            *reinterpret_cast<uint4*>(&Bs[nxt][ldRow][ldCol]) = t;
            t.x=f2tf32(w1p.x); t.y=f2tf32(w1p.y); t.z=f2tf32(w1p.z); t.w=f2tf32(w1p.w);
            *reinterpret_cast<uint4*>(&Bs[nxt][ldRow+64][ldCol]) = t;
        }
        __syncthreads();
        cur ^= 1;
    }

    #pragma unroll
    for (int mt = 0; mt < 4; mt++) {
        #pragma unroll
        for (int nt = 0; nt < 4; nt++) {
            int mg0 = mBase + wm * 64 + mt * 16 + r;
            int ng0 = nBase + wn * 32 + nt * 8 + 2 * c;
            #pragma unroll
            for (int ri = 0; ri < 2; ri++) {
                #pragma unroll
                for (int ci = 0; ci < 2; ci++) {
                    int m = mg0 + ri * 8;
                    int n = ng0 + ci;
                    if (n < N) {
                        float s = acc[mt][nt][ri * 2 + ci] + bias[n];
                        C[(size_t)m * N + n] = (s > 20.f) ? s : log1pf(expf(s));
                    }
                }
            }
        }
    }
}

// ---------------- embedding gather (float4 vectorized) ----------------
__global__ void embed_kernel(const int* __restrict__ tokens,
                             const float* __restrict__ emb,
                             float* __restrict__ resid) {
    int row = blockIdx.x;
    int t = tokens[row];
    const float4* src = reinterpret_cast<const float4*>(emb + (size_t)t * DD);
    float4* dst = reinterpret_cast<float4*>(resid + (size_t)row * DD);
    for (int i = threadIdx.x; i < DD / 4; i += blockDim.x) dst[i] = src[i];
}

// ---------------- rmsnorm -> fp16 output ----------------
__global__ void rmsnorm_h_kernel(const float* __restrict__ x,
                                 const float* __restrict__ w,
                                 __half* __restrict__ out) {
    int row = blockIdx.x;
    const float* xr = x + (size_t)row * DD;
    float s = 0.f;
    for (int i = threadIdx.x; i < DD; i += 256) { float v = xr[i]; s = fmaf(v, v, s); }
    s = warpReduceSum(s);
    __shared__ float red[8];
    int warp = threadIdx.x >> 5, lane = threadIdx.x & 31;
    if (lane == 0) red[warp] = s;
    __syncthreads();
    if (warp == 0) {
        float v = (lane < 8) ? red[lane] : 0.f;
        v = warpReduceSum(v);
        if (lane == 0) red[0] = rsqrtf(v / (float)DD + 1e-5f);
    }
    __syncthreads();
    float scale = red[0];
    __half* o = out + (size_t)row * DD;
    for (int i = threadIdx.x; i < DD; i += 256)
        o[i] = __float2half_rn(xr[i] * scale * w[i]);
}

// ---------------- depthwise causal conv1d + bias + silu (fp32 + fp16 out) ----------------
__global__ void conv_silu_kernel(const float* __restrict__ xi,
                                 const float* __restrict__ cw,
                                 const float* __restrict__ cb,
                                 float* __restrict__ out,
                                 __half* __restrict__ outh) {
    int idx = blockIdx.x * blockDim.x + threadIdx.x;
    if (idx >= BB * LL * EE) return;
    int e  = idx % EE;
    int bl = idx / EE;
    int l  = bl % LL;
    float acc = cb[e];
    #pragma unroll
    for (int k = 0; k < DCONV; k++) {
        int ls = l - (DCONV - 1) + k;
        if (ls >= 0)
            acc = fmaf(cw[e * DCONV + k],
                       xi[(size_t)(bl - (DCONV - 1) + k) * EE + e], acc);
    }
    float v = acc / (1.f + __expf(-acc));
    out[idx] = v;
    outh[idx] = __float2half_rn(v);
}

// ---------------- selective scan: 4 threads per channel (4 states each) ----------------
__global__ void __launch_bounds__(256)
scan_kernel(const float* __restrict__ delta, const float* __restrict__ x,
            const float* __restrict__ Bm, const float* __restrict__ Cm, int ldbc,
            const float* __restrict__ A_log, float* __restrict__ y) {
    int ch = blockIdx.x * 64 + (threadIdx.x >> 2);   // 0 .. BB*EE-1
    int ng = threadIdx.x & 3;                         // state group 0..3
    int b  = ch / EE;
    int e  = ch % EE;

    float a[4], h[4];
    #pragma unroll
    for (int j = 0; j < 4; j++) {
        a[j] = -expf(A_log[e * NN + ng * 4 + j]);
        h[j] = 0.f;
    }

    const size_t row0 = (size_t)b * LL;
    #pragma unroll 2
    for (int l = 0; l < LL; l++) {
        size_t row = row0 + l;
        float d  = delta[row * EE + e];
        float xv = x    [row * EE + e];
        float dx = d * xv;
        float4 Bv = *reinterpret_cast<const float4*>(Bm + row * ldbc + ng * 4);
        float4 Cv = *reinterpret_cast<const float4*>(Cm + row * ldbc + ng * 4);
        float yacc;
        h[0] = __expf(d * a[0]) * h[0] + dx * Bv.x;
        h[1] = __expf(d * a[1]) * h[1] + dx * Bv.y;
        h[2] = __expf(d * a[2]) * h[2] + dx * Bv.z;
        h[3] = __expf(d * a[3]) * h[3] + dx * Bv.w;
        yacc = h[0] * Cv.x;
        yacc = fmaf(h[1], Cv.y, yacc);
        yacc = fmaf(h[2], Cv.z, yacc);
        yacc = fmaf(h[3], Cv.w, yacc);
        yacc += __shfl_xor_sync(0xffffffffu, yacc, 1);
        yacc += __shfl_xor_sync(0xffffffffu, yacc, 2);
        if (ng == 0) y[row * EE + e] = yacc;
    }
}

// ---------------- output gating -> fp16 y (float4 vectorized) ----------------
__global__ void combine_kernel(const float* __restrict__ y,
                               const float* __restrict__ xc,
                               const float* __restrict__ wD,
                               const float* __restrict__ skip,
                               __half* __restrict__ yh) {
    int i = blockIdx.x * blockDim.x + threadIdx.x;   // float4 index
    if (i >= BB * LL * EE / 4) return;
    int e4 = (i % (EE / 4)) * 4;
    float4 yv = reinterpret_cast<const float4*>(y)[i];
    float4 xv = reinterpret_cast<const float4*>(xc)[i];
    float4 sv = reinterpret_cast<const float4*>(skip)[i];
    float4 wv = *reinterpret_cast<const float4*>(wD + e4);
    float v0 = fmaf(xv.x, wv.x, yv.x) * (sv.x / (1.f + __expf(-sv.x)));
    float v1 = fmaf(xv.y, wv.y, yv.y) * (sv.y / (1.f + __expf(-sv.y)));
    float v2 = fmaf(xv.z, wv.z, yv.z) * (sv.z / (1.f + __expf(-sv.z)));
    float v3 = fmaf(xv.w, wv.w, yv.w) * (sv.w / (1.f + __expf(-sv.w)));
    __half2 h0 = __floats2half2_rn(v0, v1);
    __half2 h1 = __floats2half2_rn(v2, v3);
    uint2 t;
    t.x = *reinterpret_cast<uint32_t*>(&h0);
    t.y = *reinterpret_cast<uint32_t*>(&h1);
    reinterpret_cast<uint2*>(yh)[i] = t;
}

// ---------------- launch ----------------
extern "C" void kernel_launch(void* const* d_in, const int* in_sizes, int n_in,
                              void* d_out, int out_size) {
    (void)in_sizes; (void)n_in; (void)out_size;

    const int*   tokens = (const int*)  d_in[0];
    const float* emb    = (const float*)d_in[1];
    const float* norm_w = (const float*)d_in[2];
    const float* skip_w = (const float*)d_in[3];
    const float* in_w   = (const float*)d_in[4];
    const float* conv_w = (const float*)d_in[5];
    const float* conv_b = (const float*)d_in[6];
    const float* Wd1    = (const float*)d_in[7];
    const float* Wd2_w  = (const float*)d_in[8];
    const float* Wd2_b  = (const float*)d_in[9];
    const float* WB     = (const float*)d_in[10];
    const float* WC     = (const float*)d_in[11];
    const float* A_log  = (const float*)d_in[12];
    const float* W_D    = (const float*)d_in[13];
    const float* out_w  = (const float*)d_in[14];
    const float* fnw    = (const float*)d_in[15];
    const float* lm     = (const float*)d_in[16];
    float* out = (float*)d_out;

    float *resid, *skip, *xi, *xc, *dbc, *delta, *y;
    cudaGetSymbolAddress((void**)&resid, g_resid);
    cudaGetSymbolAddress((void**)&skip,  g_skip);
    cudaGetSymbolAddress((void**)&xi,    g_xi);
    cudaGetSymbolAddress((void**)&xc,    g_xc);
    cudaGetSymbolAddress((void**)&dbc,   g_dbc);
    cudaGetSymbolAddress((void**)&delta, g_delta);
    cudaGetSymbolAddress((void**)&y,     g_y);

    __half *hlm, *hskip, *hin, *hout, *hWsm, *hxn, *hxc, *hy;
    cudaGetSymbolAddress((void**)&hlm,   h_lm);
    cudaGetSymbolAddress((void**)&hskip, h_skip);
    cudaGetSymbolAddress((void**)&hin,   h_in);
    cudaGetSymbolAddress((void**)&hout,  h_out);
    cudaGetSymbolAddress((void**)&hWsm,  h_Wsm);
    cudaGetSymbolAddress((void**)&hxn,   h_xn);
    cudaGetSymbolAddress((void**)&hxc,   h_xc);
    cudaGetSymbolAddress((void**)&hy,    h_y);

    // ---- weight conversions: ONE launch, 10 jobs ----
    {
        F2HJobs jj = {};
        int j = 0;
        jj.s[j] = lm;     jj.d[j] = hlm;   jj.n4[j] = VV * DD / 4;           j++;
        jj.s[j] = skip_w; jj.d[j] = hskip; jj.n4[j] = NLAYERS * EE * DD / 4; j++;
        jj.s[j] = in_w;   jj.d[j] = hin;   jj.n4[j] = NLAYERS * EE * DD / 4; j++;
        jj.s[j] = out_w;  jj.d[j] = hout;  jj.n4[j] = NLAYERS * DD * EE / 4; j++;
        for (int l = 0; l < NLAYERS; l++) {
            jj.s[j] = Wd1 + (size_t)l * DDELTA * EE;
            jj.d[j] = hWsm + (size_t)l * PKN * EE;
            jj.n4[j] = DDELTA * EE / 4; j++;
            jj.s[j] = WB + (size_t)l * NN * EE;
            jj.d[j] = hWsm + (size_t)l * PKN * EE + (size_t)DDELTA * EE;
            jj.n4[j] = NN * EE / 4; j++;
            jj.s[j] = WC + (size_t)l * NN * EE;
            jj.d[j] = hWsm + (size_t)l * PKN * EE + (size_t)(DDELTA + NN) * EE;
            jj.n4[j] = NN * EE / 4; j++;
        }
        f2h_multi<<<dim3(1184, (unsigned)j, 1), 256>>>(jj);
    }

    const int totE = BB * LL * EE;
    const dim3 gE2((EE  + 127) / 128, ML / 128, 2);  // skip + in fused
    const dim3 gP ((PKN + 127) / 128, ML / 128, 1);  // packed d1|B|C
    const dim3 gDe((EE  + 127) / 128, ML / 128, 1);  // tf32 softplus
    const dim3 gO ((DD  + 127) / 128, ML / 128, 1);
    const dim3 gV ((VV  + 127) / 128, ML / 128, 1);

    embed_kernel<<<ML, 256>>>(tokens, emb, resid);

    for (int lyr = 0; lyr < NLAYERS; ++lyr) {
        rmsnorm_h_kernel<<<ML, 256>>>(resid, norm_w + lyr * DD, hxn);

        gemm_h<0><<<gE2, 256>>>(hxn,
            hskip + (size_t)lyr * EE * DD, hin + (size_t)lyr * EE * DD,
            skip, xi, ML, EE, DD);

        conv_silu_kernel<<<(totE + 255) / 256, 256>>>(xi, conv_w + lyr * EE * DCONV,
                                                      conv_b + lyr * EE, xc, hxc);

        // packed small GEMM: [d1 48 | B 16 | C 16] = xc @ Wsm^T
        gemm_h<0><<<gP, 256>>>(hxc, hWsm + (size_t)lyr * PKN * EE, nullptr,
                               dbc, nullptr, ML, PKN, EE);

        gemm_tf32_sp<<<gDe, 256>>>(dbc, PKN, Wd2_w + (size_t)lyr * EE * DDELTA,
                                   Wd2_b + lyr * EE, delta, ML, EE, DDELTA);

        scan_kernel<<<BB * EE * 4 / 256, 256>>>(delta, xc,
                                                dbc + DDELTA, dbc + DDELTA + NN, PKN,
                                                A_log + lyr * EE * NN, y);

        combine_kernel<<<(totE / 4 + 255) / 256, 256>>>(y, xc, W_D + lyr * EE, skip, hy);

        gemm_h<1><<<gO, 256>>>(hy, hout + (size_t)lyr * DD * EE, nullptr,
                               resid, nullptr, ML, DD, EE);
    }

    rmsnorm_h_kernel<<<ML, 256>>>(resid, fnw, hxn);
    gemm_h<0><<<gV, 256>>>(hxn, hlm, nullptr, out, nullptr, ML, VV, DD);
}

// round 15
// speedup vs baseline: 1.2668x; 1.0033x over previous
#include <cuda_runtime.h>
#include <cuda_fp16.h>
#include <math.h>
#include <stdint.h>

// ---------------- problem constants ----------------
#define BB      2
#define LL      1024
#define DD      768
#define EE      1536
#define NN      16
#define DDELTA  48
#define DCONV   4
#define VV      50280
#define NLAYERS 2
#define ML      (BB*LL)   // 2048 rows
#define PKN     (DDELTA + 2*NN)   // 80 packed rows: [delta1 48 | B 16 | C 16]

// ---------------- scratch (no allocs allowed) ----------------
__device__ float g_resid[BB*LL*DD];
__device__ float g_skip[BB*LL*EE];
__device__ float g_xi  [BB*LL*EE];
__device__ float g_xc  [BB*LL*EE];
__device__ float g_dbc [ML*PKN];          // packed [d1 | B | C] per row
__device__ float g_delta[BB*LL*EE];
__device__ float g_y   [BB*LL*EE];

// fp16 weight / activation copies
__device__ __align__(16) __half h_lm  [VV*DD];
__device__ __align__(16) __half h_skip[NLAYERS*EE*DD];
__device__ __align__(16) __half h_in  [NLAYERS*EE*DD];
__device__ __align__(16) __half h_out [NLAYERS*DD*EE];
__device__ __align__(16) __half h_Wsm [NLAYERS*PKN*EE];   // packed small weights
__device__ __align__(16) __half h_xn  [ML*DD];
__device__ __align__(16) __half h_xc  [ML*EE];
__device__ __align__(16) __half h_y   [ML*EE];

// ---------------- helpers ----------------
__inline__ __device__ float warpReduceSum(float v) {
    #pragma unroll
    for (int o = 16; o > 0; o >>= 1) v += __shfl_down_sync(0xffffffffu, v, o);
    return v;
}

__device__ __forceinline__ uint32_t f2tf32(float f) {
    uint32_t u;
    asm("cvt.rna.tf32.f32 %0, %1;" : "=r"(u) : "f"(f));
    return u;
}

__device__ __forceinline__ void mma_f16(float* c, const uint32_t* a, const uint32_t* b) {
    asm volatile(
        "mma.sync.aligned.m16n8k16.row.col.f32.f16.f16.f32 "
        "{%0,%1,%2,%3}, {%4,%5,%6,%7}, {%8,%9}, {%0,%1,%2,%3};\n"
        : "+f"(c[0]), "+f"(c[1]), "+f"(c[2]), "+f"(c[3])
        : "r"(a[0]), "r"(a[1]), "r"(a[2]), "r"(a[3]), "r"(b[0]), "r"(b[1]));
}

__device__ __forceinline__ void mma_tf32(float* c, const uint32_t* a, const uint32_t* b) {
    asm volatile(
        "mma.sync.aligned.m16n8k8.row.col.f32.tf32.tf32.f32 "
        "{%0,%1,%2,%3}, {%4,%5,%6,%7}, {%8,%9}, {%0,%1,%2,%3};\n"
        : "+f"(c[0]), "+f"(c[1]), "+f"(c[2]), "+f"(c[3])
        : "r"(a[0]), "r"(a[1]), "r"(a[2]), "r"(a[3]), "r"(b[0]), "r"(b[1]));
}

__device__ __forceinline__ void ldsm_x4(uint32_t& r0, uint32_t& r1, uint32_t& r2,
                                        uint32_t& r3, uint32_t saddr) {
    asm volatile("ldmatrix.sync.aligned.m8n8.x4.shared.b16 {%0,%1,%2,%3}, [%4];"
                 : "=r"(r0), "=r"(r1), "=r"(r2), "=r"(r3) : "r"(saddr));
}

__device__ __forceinline__ void cp16(uint32_t dst, const void* src) {
    asm volatile("cp.async.cg.shared.global [%0], [%1], 16;" :: "r"(dst), "l"(src));
}
__device__ __forceinline__ void cp16p(uint32_t dst, const void* src, int sz) {
    asm volatile("cp.async.cg.shared.global [%0], [%1], 16, %2;"
                 :: "r"(dst), "l"(src), "r"(sz));
}
__device__ __forceinline__ void cp_commit() {
    asm volatile("cp.async.commit_group;");
}
template<int NWAIT>
__device__ __forceinline__ void cp_wait() {
    asm volatile("cp.async.wait_group %0;" :: "n"(NWAIT));
}

// ---------------- fp32 -> fp16 convert: single launch ----------------
struct F2HJobs {
    const float* s[12];
    __half*      d[12];
    int          n4[12];
};

__global__ void f2h_multi(F2HJobs jobs) {
    int j = blockIdx.y;
    int n4 = jobs.n4[j];
    const float4* s = reinterpret_cast<const float4*>(jobs.s[j]);
    uint2*        d = reinterpret_cast<uint2*>(jobs.d[j]);
    for (int i = blockIdx.x * blockDim.x + threadIdx.x; i < n4;
         i += gridDim.x * blockDim.x) {
        float4 v = s[i];
        __half2 h0 = __floats2half2_rn(v.x, v.y);
        __half2 h1 = __floats2half2_rn(v.z, v.w);
        uint2 t;
        t.x = *reinterpret_cast<uint32_t*>(&h0);
        t.y = *reinterpret_cast<uint32_t*>(&h1);
        d[i] = t;
    }
}

// ================= FP16 HMMA GEMM, 128x128 CTA, 2-stage static smem (PINNED) =================
#define SSH 40                         // halfs per smem row (32 + pad 8)
#define HBUF (128 * SSH * 2)           // bytes per buffer

__device__ __forceinline__ void issue_chunk(uint32_t sAbuf, uint32_t sBbuf,
                                            const __half* __restrict__ Ab,
                                            const __half* __restrict__ Wb,
                                            int K, int k0, int nBase, int N, int tid) {
    #pragma unroll
    for (int f = 0; f < 2; f++) {
        int idx = f * 256 + tid;
        int r = idx >> 2, g = idx & 3;
        cp16(sAbuf + (uint32_t)(r * SSH + g * 8) * 2, Ab + (size_t)r * K + k0 + g * 8);
        int sz = (nBase + r < N) ? 16 : 0;
        cp16p(sBbuf + (uint32_t)(r * SSH + g * 8) * 2, Wb + (size_t)r * K + k0 + g * 8, sz);
    }
}

template<int EPI>
__global__ void __launch_bounds__(256)
gemm_h(const __half* __restrict__ A,
       const __half* __restrict__ W0, const __half* __restrict__ W1,
       float* __restrict__ C0, float* __restrict__ C1,
       int M, int N, int K) {
    __shared__ __half As[2][128][SSH];
    __shared__ __half Bs[2][128][SSH];

    const __half* W = blockIdx.z ? W1 : W0;
    float*        C = blockIdx.z ? C1 : C0;

    const int tid  = threadIdx.x;
    const int lane = tid & 31;
    const int warp = tid >> 5;
    const int wm   = warp >> 2;
    const int wn   = warp & 3;
    const int r    = lane >> 2;
    const int c    = lane & 3;

    const int mBase = blockIdx.y * 128;
    const int nBase = blockIdx.x * 128;
    const int nk = K / 32;
    const __half* Ab = A + (size_t)mBase * K;
    const __half* Wb = W + (size_t)nBase * K;

    const int mat  = lane >> 3;
    const int mrow = lane & 7;
    const int aOff = (((wm * 64) + (mat & 1) * 8 + mrow) * SSH + ((mat >> 1) * 8)) * 2;
    const int bOff = (((wn * 32) + (mat >> 1) * 8 + mrow) * SSH + ((mat & 1) * 8)) * 2;
    const uint32_t sA = (uint32_t)__cvta_generic_to_shared(&As[0][0][0]);
    const uint32_t sB = (uint32_t)__cvta_generic_to_shared(&Bs[0][0][0]);

    float acc[4][4][4];
    #pragma unroll
    for (int i = 0; i < 4; i++)
        #pragma unroll
        for (int j = 0; j < 4; j++)
            #pragma unroll
            for (int k = 0; k < 4; k++) acc[i][j][k] = 0.f;

    issue_chunk(sA, sB, Ab, Wb, K, 0, nBase, N, tid);
    cp_commit();
    if (nk > 1) {
        issue_chunk(sA + HBUF, sB + HBUF, Ab, Wb, K, 32, nBase, N, tid);
        cp_commit();
    }

    for (int ch = 0; ch < nk; ch++) {
        if (ch + 1 < nk) cp_wait<1>(); else cp_wait<0>();
        __syncthreads();

        const uint32_t aBase = sA + (ch & 1) * HBUF + aOff;
        const uint32_t bBase = sB + (ch & 1) * HBUF + bOff;
        #pragma unroll
        for (int ks = 0; ks < 32; ks += 16) {
            uint32_t af[4][4], bf[4][2];
            #pragma unroll
            for (int mt = 0; mt < 4; mt++)
                ldsm_x4(af[mt][0], af[mt][1], af[mt][2], af[mt][3],
                        aBase + (uint32_t)(mt * 16 * SSH + ks) * 2);
            #pragma unroll
            for (int np = 0; np < 2; np++)
                ldsm_x4(bf[2*np][0], bf[2*np][1], bf[2*np+1][0], bf[2*np+1][1],
                        bBase + (uint32_t)(np * 16 * SSH + ks) * 2);
            #pragma unroll
            for (int mt = 0; mt < 4; mt++)
                #pragma unroll
                for (int nt = 0; nt < 4; nt++)
                    mma_f16(acc[mt][nt], af[mt], bf[nt]);
        }
        __syncthreads();

        if (ch + 2 < nk) {
            issue_chunk(sA + (ch & 1) * HBUF, sB + (ch & 1) * HBUF,
                        Ab, Wb, K, (ch + 2) * 32, nBase, N, tid);
            cp_commit();
        }
    }

    #pragma unroll
    for (int mt = 0; mt < 4; mt++) {
        #pragma unroll
        for (int nt = 0; nt < 4; nt++) {
            int mg0 = mBase + wm * 64 + mt * 16 + r;
            int ng0 = nBase + wn * 32 + nt * 8 + 2 * c;
            #pragma unroll
            for (int ri = 0; ri < 2; ri++) {
                #pragma unroll
                for (int ci = 0; ci < 2; ci++) {
                    int m = mg0 + ri * 8;
                    int n = ng0 + ci;
                    float v = acc[mt][nt][ri * 2 + ci];
                    if (n < N) {
                        size_t idx = (size_t)m * N + n;
                        if (EPI == 1) C[idx] += v; else C[idx] = v;
                    }
                }
            }
        }
    }
}

// ================= FP16 HMMA GEMM, 64x128 CTA (fill-bound launches) =================
// Same 2-stage structure, warp tile 32x32, 8 warps. ~30.7 KB smem, ~80 regs.
#define ABUF64 (64 * SSH * 2)
#define BBUF64 (128 * SSH * 2)

__device__ __forceinline__ void issue_chunk64(uint32_t sAbuf, uint32_t sBbuf,
                                              const __half* __restrict__ Ab,
                                              const __half* __restrict__ Wb,
                                              int K, int k0, int nBase, int N, int tid) {
    {   // A: 64 rows, 1 float4 per thread
        int r = tid >> 2, g = tid & 3;
        cp16(sAbuf + (uint32_t)(r * SSH + g * 8) * 2, Ab + (size_t)r * K + k0 + g * 8);
    }
    #pragma unroll
    for (int f = 0; f < 2; f++) {   // B: 128 rows
        int idx = f * 256 + tid;
        int r = idx >> 2, g = idx & 3;
        int sz = (nBase + r < N) ? 16 : 0;
        cp16p(sBbuf + (uint32_t)(r * SSH + g * 8) * 2, Wb + (size_t)r * K + k0 + g * 8, sz);
    }
}

template<int EPI>
__global__ void __launch_bounds__(256)
gemm_h64(const __half* __restrict__ A, const __half* __restrict__ W,
         float* __restrict__ C, int M, int N, int K) {
    __shared__ __half As[2][64][SSH];
    __shared__ __half Bs[2][128][SSH];

    const int tid  = threadIdx.x;
    const int lane = tid & 31;
    const int warp = tid >> 5;
    const int wm   = warp >> 2;          // 0..1 (32-row slab)
    const int wn   = warp & 3;           // 0..3 (32-col slab)
    const int r    = lane >> 2;
    const int c    = lane & 3;

    const int mBase = blockIdx.y * 64;
    const int nBase = blockIdx.x * 128;
    const int nk = K / 32;
    const __half* Ab = A + (size_t)mBase * K;
    const __half* Wb = W + (size_t)nBase * K;

    const int mat  = lane >> 3;
    const int mrow = lane & 7;
    const int aOff = (((wm * 32) + (mat & 1) * 8 + mrow) * SSH + ((mat >> 1) * 8)) * 2;
    const int bOff = (((wn * 32) + (mat >> 1) * 8 + mrow) * SSH + ((mat & 1) * 8)) * 2;
    const uint32_t sA = (uint32_t)__cvta_generic_to_shared(&As[0][0][0]);
    const uint32_t sB = (uint32_t)__cvta_generic_to_shared(&Bs[0][0][0]);

    float acc[2][4][4];
    #pragma unroll
    for (int i = 0; i < 2; i++)
        #pragma unroll
        for (int j = 0; j < 4; j++)
            #pragma unroll
            for (int k = 0; k < 4; k++) acc[i][j][k] = 0.f;

    issue_chunk64(sA, sB, Ab, Wb, K, 0, nBase, N, tid);
    cp_commit();
    if (nk > 1) {
        issue_chunk64(sA + ABUF64, sB + BBUF64, Ab, Wb, K, 32, nBase, N, tid);
        cp_commit();
    }

    for (int ch = 0; ch < nk; ch++) {
        if (ch + 1 < nk) cp_wait<1>(); else cp_wait<0>();
        __syncthreads();

        const uint32_t aBase = sA + (ch & 1) * ABUF64 + aOff;
        const uint32_t bBase = sB + (ch & 1) * BBUF64 + bOff;
        #pragma unroll
        for (int ks = 0; ks < 32; ks += 16) {
            uint32_t af[2][4], bf[4][2];
            #pragma unroll
            for (int mt = 0; mt < 2; mt++)
                ldsm_x4(af[mt][0], af[mt][1], af[mt][2], af[mt][3],
                        aBase + (uint32_t)(mt * 16 * SSH + ks) * 2);
            #pragma unroll
            for (int np = 0; np < 2; np++)
                ldsm_x4(bf[2*np][0], bf[2*np][1], bf[2*np+1][0], bf[2*np+1][1],
                        bBase + (uint32_t)(np * 16 * SSH + ks) * 2);
            #pragma unroll
            for (int mt = 0; mt < 2; mt++)
                #pragma unroll
                for (int nt = 0; nt < 4; nt++)
                    mma_f16(acc[mt][nt], af[mt], bf[nt]);
        }
        __syncthreads();

        if (ch + 2 < nk) {
            issue_chunk64(sA + (ch & 1) * ABUF64, sB + (ch & 1) * BBUF64,
                          Ab, Wb, K, (ch + 2) * 32, nBase, N, tid);
            cp_commit();
        }
    }

    #pragma unroll
    for (int mt = 0; mt < 2; mt++) {
        #pragma unroll
        for (int nt = 0; nt < 4; nt++) {
            int mg0 = mBase + wm * 32 + mt * 16 + r;
            int ng0 = nBase + wn * 32 + nt * 8 + 2 * c;
            #pragma unroll
            for (int ri = 0; ri < 2; ri++) {
                #pragma unroll
                for (int ci = 0; ci < 2; ci++) {
                    int m = mg0 + ri * 8;
                    int n = ng0 + ci;
                    float v = acc[mt][nt][ri * 2 + ci];
                    if (n < N) {
                        size_t idx = (size_t)m * N + n;
                        if (EPI == 1) C[idx] += v; else C[idx] = v;
                    }
                }
            }
        }
    }
}

// ---------------- TF32 GEMM with softplus epilogue (K=48 path, strided A) ----------------
#define SST 20
__global__ void __launch_bounds__(256)
gemm_tf32_sp(const float* __restrict__ A, int lda,
             const float* __restrict__ W,
             const float* __restrict__ bias, float* __restrict__ C,
             int M, int N, int K) {
    __shared__ uint32_t As[2][128][SST];
    __shared__ uint32_t Bs[2][128][SST];

    const int tid  = threadIdx.x;
    const int lane = tid & 31;
    const int warp = tid >> 5;
    const int wm   = warp >> 2;
    const int wn   = warp & 3;
    const int r    = lane >> 2;
    const int c    = lane & 3;

    const int ldRow = tid >> 2;
    const int ldCol = (tid & 3) * 4;

    const int mBase = blockIdx.y * 128;
    const int nBase = blockIdx.x * 128;
    const int nk = K / 16;

    const int mat = lane >> 3;
    const int mrow = lane & 7;
    const int aOff = (((wm * 64) + (mat & 1) * 8 + mrow) * SST + ((mat >> 1) * 4)) * 4;
    const int bOff = (((wn * 32) + (mat >> 1) * 8 + mrow) * SST + ((mat & 1) * 4)) * 4;
    const uint32_t sA = (uint32_t)__cvta_generic_to_shared(&As[0][0][0]);
    const uint32_t sB = (uint32_t)__cvta_generic_to_shared(&Bs[0][0][0]);
    const int BUF = 128 * SST * 4;

    float acc[4][4][4];
    #pragma unroll
    for (int i = 0; i < 4; i++)
        #pragma unroll
        for (int j = 0; j < 4; j++)
            #pragma unroll
            for (int k = 0; k < 4; k++) acc[i][j][k] = 0.f;

    float4 a0p, a1p, w0p, w1p;
    {
        const float* ap = A + (size_t)(mBase + ldRow) * lda + ldCol;
        a0p = *reinterpret_cast<const float4*>(ap);
        a1p = *reinterpret_cast<const float4*>(ap + (size_t)64 * lda);
        int n0 = nBase + ldRow, n1 = n0 + 64;
        w0p = make_float4(0.f,0.f,0.f,0.f);
        w1p = w0p;
        if (n0 < N) w0p = *reinterpret_cast<const float4*>(W + (size_t)n0 * K + ldCol);
        if (n1 < N) w1p = *reinterpret_cast<const float4*>(W + (size_t)n1 * K + ldCol);
    }
    {
        uint4 t;
        t.x=f2tf32(a0p.x); t.y=f2tf32(a0p.y); t.z=f2tf32(a0p.z); t.w=f2tf32(a0p.w);
        *reinterpret_cast<uint4*>(&As[0][ldRow][ldCol]) = t;
        t.x=f2tf32(a1p.x); t.y=f2tf32(a1p.y); t.z=f2tf32(a1p.z); t.w=f2tf32(a1p.w);
        *reinterpret_cast<uint4*>(&As[0][ldRow+64][ldCol]) = t;
        t.x=f2tf32(w0p.x); t.y=f2tf32(w0p.y); t.z=f2tf32(w0p.z); t.w=f2tf32(w0p.w);
        *reinterpret_cast<uint4*>(&Bs[0][ldRow][ldCol]) = t;
        t.x=f2tf32(w1p.x); t.y=f2tf32(w1p.y); t.z=f2tf32(w1p.z); t.w=f2tf32(w1p.w);
        *reinterpret_cast<uint4*>(&Bs[0][ldRow+64][ldCol]) = t;
    }
    __syncthreads();

    int cur = 0;
    for (int ch = 0; ch < nk; ch++) {
        if (ch + 1 < nk) {
            int k0 = (ch + 1) * 16;
            const float* ap = A + (size_t)(mBase + ldRow) * lda + k0 + ldCol;
            a0p = *reinterpret_cast<const float4*>(ap);
            a1p = *reinterpret_cast<const float4*>(ap + (size_t)64 * lda);
            int n0 = nBase + ldRow, n1 = n0 + 64;
            w0p = make_float4(0.f,0.f,0.f,0.f);
            w1p = w0p;
            if (n0 < N) w0p = *reinterpret_cast<const float4*>(W + (size_t)n0 * K + k0 + ldCol);
            if (n1 < N) w1p = *reinterpret_cast<const float4*>(W + (size_t)n1 * K + k0 + ldCol);
        }

        const uint32_t aBase = sA + cur * BUF + aOff;
        const uint32_t bBase = sB + cur * BUF + bOff;
        #pragma unroll
        for (int ks = 0; ks < 16; ks += 8) {
            uint32_t af[4][4], bf[4][2];
            #pragma unroll
            for (int mt = 0; mt < 4; mt++)
                ldsm_x4(af[mt][0], af[mt][1], af[mt][2], af[mt][3],
                        aBase + (mt * 16 * SST + ks) * 4);
            #pragma unroll
            for (int np = 0; np < 2; np++)
                ldsm_x4(bf[2*np][0], bf[2*np][1], bf[2*np+1][0], bf[2*np+1][1],
                        bBase + (np * 16 * SST + ks) * 4);
            #pragma unroll
            for (int mt = 0; mt < 4; mt++)
                #pragma unroll
                for (int nt = 0; nt < 4; nt++)
                    mma_tf32(acc[mt][nt], af[mt], bf[nt]);
        }

        if (ch + 1 < nk) {
            int nxt = cur ^ 1;
            uint4 t;
            t.x=f2tf32(a0p.x); t.y=f2tf32(a0p.y); t.z=f2tf32(a0p.z); t.w=f2tf32(a0p.w);
            *reinterpret_cast<uint4*>(&As[nxt][ldRow][ldCol]) = t;
            t.x=f2tf32(a1p.x); t.y=f2tf32(a1p.y); t.z=f2tf32(a1p.z); t.w=f2tf32(a1p.w);
            *reinterpret_cast<uint4*>(&As[nxt][ldRow+64][ldCol]) = t;
            t.x=f2tf32(w0p.x); t.y=f2tf32(w0p.y); t.z=f2tf32(w0p.z); t.w=f2tf32(w0p.w);
            *reinterpret_cast<uint4*>(&Bs[nxt][ldRow][ldCol]) = t;
            t.x=f2tf32(w1p.x); t.y=f2tf32(w1p.y); t.z=f2tf32(w1p.z); t.w=f2tf32(w1p.w);
            *reinterpret_cast<uint4*>(&Bs[nxt][ldRow+64][ldCol]) = t;
        }
        __syncthreads();
        cur ^= 1;
    }

    #pragma unroll
    for (int mt = 0; mt < 4; mt++) {
        #pragma unroll
        for (int nt = 0; nt < 4; nt++) {
            int mg0 = mBase + wm * 64 + mt * 16 + r;
            int ng0 = nBase + wn * 32 + nt * 8 + 2 * c;
            #pragma unroll
            for (int ri = 0; ri < 2; ri++) {
                #pragma unroll
                for (int ci = 0; ci < 2; ci++) {
                    int m = mg0 + ri * 8;
                    int n = ng0 + ci;
                    if (n < N) {
                        float s = acc[mt][nt][ri * 2 + ci] + bias[n];
                        C[(size_t)m * N + n] = (s > 20.f) ? s : log1pf(expf(s));
                    }
                }
            }
        }
    }
}

// ---------------- embedding gather (float4 vectorized) ----------------
__global__ void embed_kernel(const int* __restrict__ tokens,
                             const float* __restrict__ emb,
                             float* __restrict__ resid) {
    int row = blockIdx.x;
    int t = tokens[row];
    const float4* src = reinterpret_cast<const float4*>(emb + (size_t)t * DD);
    float4* dst = reinterpret_cast<float4*>(resid + (size_t)row * DD);
    for (int i = threadIdx.x; i < DD / 4; i += blockDim.x) dst[i] = src[i];
}

// ---------------- rmsnorm -> fp16 output ----------------
__global__ void rmsnorm_h_kernel(const float* __restrict__ x,
                                 const float* __restrict__ w,
                                 __half* __restrict__ out) {
    int row = blockIdx.x;
    const float* xr = x + (size_t)row * DD;
    float s = 0.f;
    for (int i = threadIdx.x; i < DD; i += 256) { float v = xr[i]; s = fmaf(v, v, s); }
    s = warpReduceSum(s);
    __shared__ float red[8];
    int warp = threadIdx.x >> 5, lane = threadIdx.x & 31;
    if (lane == 0) red[warp] = s;
    __syncthreads();
    if (warp == 0) {
        float v = (lane < 8) ? red[lane] : 0.f;
        v = warpReduceSum(v);
        if (lane == 0) red[0] = rsqrtf(v / (float)DD + 1e-5f);
    }
    __syncthreads();
    float scale = red[0];
    __half* o = out + (size_t)row * DD;
    for (int i = threadIdx.x; i < DD; i += 256)
        o[i] = __float2half_rn(xr[i] * scale * w[i]);
}

// ---------------- depthwise causal conv1d + bias + silu (fp32 + fp16 out) ----------------
__global__ void conv_silu_kernel(const float* __restrict__ xi,
                                 const float* __restrict__ cw,
                                 const float* __restrict__ cb,
                                 float* __restrict__ out,
                                 __half* __restrict__ outh) {
    int idx = blockIdx.x * blockDim.x + threadIdx.x;
    if (idx >= BB * LL * EE) return;
    int e  = idx % EE;
    int bl = idx / EE;
    int l  = bl % LL;
    float acc = cb[e];
    #pragma unroll
    for (int k = 0; k < DCONV; k++) {
        int ls = l - (DCONV - 1) + k;
        if (ls >= 0)
            acc = fmaf(cw[e * DCONV + k],
                       xi[(size_t)(bl - (DCONV - 1) + k) * EE + e], acc);
    }
    float v = acc / (1.f + __expf(-acc));
    out[idx] = v;
    outh[idx] = __float2half_rn(v);
}

// ---------------- selective scan: 4 threads per channel (4 states each) ----------------
__global__ void __launch_bounds__(256)
scan_kernel(const float* __restrict__ delta, const float* __restrict__ x,
            const float* __restrict__ Bm, const float* __restrict__ Cm, int ldbc,
            const float* __restrict__ A_log, float* __restrict__ y) {
    int ch = blockIdx.x * 64 + (threadIdx.x >> 2);   // 0 .. BB*EE-1
    int ng = threadIdx.x & 3;                         // state group 0..3
    int b  = ch / EE;
    int e  = ch % EE;

    float a[4], h[4];
    #pragma unroll
    for (int j = 0; j < 4; j++) {
        a[j] = -expf(A_log[e * NN + ng * 4 + j]);
        h[j] = 0.f;
    }

    const size_t row0 = (size_t)b * LL;
    #pragma unroll 2
    for (int l = 0; l < LL; l++) {
        size_t row = row0 + l;
        float d  = delta[row * EE + e];
        float xv = x    [row * EE + e];
        float dx = d * xv;
        float4 Bv = *reinterpret_cast<const float4*>(Bm + row * ldbc + ng * 4);
        float4 Cv = *reinterpret_cast<const float4*>(Cm + row * ldbc + ng * 4);
        float yacc;
        h[0] = __expf(d * a[0]) * h[0] + dx * Bv.x;
        h[1] = __expf(d * a[1]) * h[1] + dx * Bv.y;
        h[2] = __expf(d * a[2]) * h[2] + dx * Bv.z;
        h[3] = __expf(d * a[3]) * h[3] + dx * Bv.w;
        yacc = h[0] * Cv.x;
        yacc = fmaf(h[1], Cv.y, yacc);
        yacc = fmaf(h[2], Cv.z, yacc);
        yacc = fmaf(h[3], Cv.w, yacc);
        yacc += __shfl_xor_sync(0xffffffffu, yacc, 1);
        yacc += __shfl_xor_sync(0xffffffffu, yacc, 2);
        if (ng == 0) y[row * EE + e] = yacc;
    }
}

// ---------------- output gating -> fp16 y (float4 vectorized) ----------------
__global__ void combine_kernel(const float* __restrict__ y,
                               const float* __restrict__ xc,
                               const float* __restrict__ wD,
                               const float* __restrict__ skip,
                               __half* __restrict__ yh) {
    int i = blockIdx.x * blockDim.x + threadIdx.x;   // float4 index
    if (i >= BB * LL * EE / 4) return;
    int e4 = (i % (EE / 4)) * 4;
    float4 yv = reinterpret_cast<const float4*>(y)[i];
    float4 xv = reinterpret_cast<const float4*>(xc)[i];
    float4 sv = reinterpret_cast<const float4*>(skip)[i];
    float4 wv = *reinterpret_cast<const float4*>(wD + e4);
    float v0 = fmaf(xv.x, wv.x, yv.x) * (sv.x / (1.f + __expf(-sv.x)));
    float v1 = fmaf(xv.y, wv.y, yv.y) * (sv.y / (1.f + __expf(-sv.y)));
    float v2 = fmaf(xv.z, wv.z, yv.z) * (sv.z / (1.f + __expf(-sv.z)));
    float v3 = fmaf(xv.w, wv.w, yv.w) * (sv.w / (1.f + __expf(-sv.w)));
    __half2 h0 = __floats2half2_rn(v0, v1);
    __half2 h1 = __floats2half2_rn(v2, v3);
    uint2 t;
    t.x = *reinterpret_cast<uint32_t*>(&h0);
    t.y = *reinterpret_cast<uint32_t*>(&h1);
    reinterpret_cast<uint2*>(yh)[i] = t;
}

// ---------------- launch ----------------
extern "C" void kernel_launch(void* const* d_in, const int* in_sizes, int n_in,
                              void* d_out, int out_size) {
    (void)in_sizes; (void)n_in; (void)out_size;

    const int*   tokens = (const int*)  d_in[0];
    const float* emb    = (const float*)d_in[1];
    const float* norm_w = (const float*)d_in[2];
    const float* skip_w = (const float*)d_in[3];
    const float* in_w   = (const float*)d_in[4];
    const float* conv_w = (const float*)d_in[5];
    const float* conv_b = (const float*)d_in[6];
    const float* Wd1    = (const float*)d_in[7];
    const float* Wd2_w  = (const float*)d_in[8];
    const float* Wd2_b  = (const float*)d_in[9];
    const float* WB     = (const float*)d_in[10];
    const float* WC     = (const float*)d_in[11];
    const float* A_log  = (const float*)d_in[12];
    const float* W_D    = (const float*)d_in[13];
    const float* out_w  = (const float*)d_in[14];
    const float* fnw    = (const float*)d_in[15];
    const float* lm     = (const float*)d_in[16];
    float* out = (float*)d_out;

    float *resid, *skip, *xi, *xc, *dbc, *delta, *y;
    cudaGetSymbolAddress((void**)&resid, g_resid);
    cudaGetSymbolAddress((void**)&skip,  g_skip);
    cudaGetSymbolAddress((void**)&xi,    g_xi);
    cudaGetSymbolAddress((void**)&xc,    g_xc);
    cudaGetSymbolAddress((void**)&dbc,   g_dbc);
    cudaGetSymbolAddress((void**)&delta, g_delta);
    cudaGetSymbolAddress((void**)&y,     g_y);

    __half *hlm, *hskip, *hin, *hout, *hWsm, *hxn, *hxc, *hy;
    cudaGetSymbolAddress((void**)&hlm,   h_lm);
    cudaGetSymbolAddress((void**)&hskip, h_skip);
    cudaGetSymbolAddress((void**)&hin,   h_in);
    cudaGetSymbolAddress((void**)&hout,  h_out);
    cudaGetSymbolAddress((void**)&hWsm,  h_Wsm);
    cudaGetSymbolAddress((void**)&hxn,   h_xn);
    cudaGetSymbolAddress((void**)&hxc,   h_xc);
    cudaGetSymbolAddress((void**)&hy,    h_y);

    // ---- weight conversions: ONE launch, 10 jobs ----
    {
        F2HJobs jj = {};
        int j = 0;
        jj.s[j] = lm;     jj.d[j] = hlm;   jj.n4[j] = VV * DD / 4;           j++;
        jj.s[j] = skip_w; jj.d[j] = hskip; jj.n4[j] = NLAYERS * EE * DD / 4; j++;
        jj.s[j] = in_w;   jj.d[j] = hin;   jj.n4[j] = NLAYERS * EE * DD / 4; j++;
        jj.s[j] = out_w;  jj.d[j] = hout;  jj.n4[j] = NLAYERS * DD * EE / 4; j++;
        for (int l = 0; l < NLAYERS; l++) {
            jj.s[j] = Wd1 + (size_t)l * DDELTA * EE;
            jj.d[j] = hWsm + (size_t)l * PKN * EE;
            jj.n4[j] = DDELTA * EE / 4; j++;
            jj.s[j] = WB + (size_t)l * NN * EE;
            jj.d[j] = hWsm + (size_t)l * PKN * EE + (size_t)DDELTA * EE;
            jj.n4[j] = NN * EE / 4; j++;
            jj.s[j] = WC + (size_t)l * NN * EE;
            jj.d[j] = hWsm + (size_t)l * PKN * EE + (size_t)(DDELTA + NN) * EE;
            jj.n4[j] = NN * EE / 4; j++;
        }
        f2h_multi<<<dim3(1184, (unsigned)j, 1), 256>>>(jj);
    }

    const int totE = BB * LL * EE;
    const dim3 gE2((EE  + 127) / 128, ML / 128, 2);  // skip + in fused
    const dim3 gP ((PKN + 127) / 128, ML / 64);      // packed d1|B|C (64-row tiles)
    const dim3 gDe((EE  + 127) / 128, ML / 128, 1);  // tf32 softplus
    const dim3 gO ((DD  + 127) / 128, ML / 64);      // out proj (64-row tiles)
    const dim3 gV ((VV  + 127) / 128, ML / 128, 1);

    embed_kernel<<<ML, 256>>>(tokens, emb, resid);

    for (int lyr = 0; lyr < NLAYERS; ++lyr) {
        rmsnorm_h_kernel<<<ML, 256>>>(resid, norm_w + lyr * DD, hxn);

        gemm_h<0><<<gE2, 256>>>(hxn,
            hskip + (size_t)lyr * EE * DD, hin + (size_t)lyr * EE * DD,
            skip, xi, ML, EE, DD);

        conv_silu_kernel<<<(totE + 255) / 256, 256>>>(xi, conv_w + lyr * EE * DCONV,
                                                      conv_b + lyr * EE, xc, hxc);

        // packed small GEMM: [d1 48 | B 16 | C 16] = xc @ Wsm^T (64-row tiles)
        gemm_h64<0><<<gP, 256>>>(hxc, hWsm + (size_t)lyr * PKN * EE,
                                 dbc, ML, PKN, EE);

        gemm_tf32_sp<<<gDe, 256>>>(dbc, PKN, Wd2_w + (size_t)lyr * EE * DDELTA,
                                   Wd2_b + lyr * EE, delta, ML, EE, DDELTA);

        scan_kernel<<<BB * EE * 4 / 256, 256>>>(delta, xc,
                                                dbc + DDELTA, dbc + DDELTA + NN, PKN,
                                                A_log + lyr * EE * NN, y);

        combine_kernel<<<(totE / 4 + 255) / 256, 256>>>(y, xc, W_D + lyr * EE, skip, hy);

        gemm_h64<1><<<gO, 256>>>(hy, hout + (size_t)lyr * DD * EE,
                                 resid, ML, DD, EE);
    }

    rmsnorm_h_kernel<<<ML, 256>>>(resid, fnw, hxn);
    gemm_h<0><<<gV, 256>>>(hxn, hlm, nullptr, out, nullptr, ML, VV, DD);
}